// round 1
// baseline (speedup 1.0000x reference)
#include <cuda_runtime.h>
#include <cuda_bf16.h>
#include <math.h>

// ---------------------------------------------------------------------------
// GCN: 3x GCNConv(relu) + global_mean_pool + linear
// N=50000 nodes, E=600000 edges, HIDDEN=128, G=128 graphs, C=5 classes
// ---------------------------------------------------------------------------

#define MAXN 50000
#define MAXE 600000
#define H 128
#define GMAX 8

// scratch (device globals -- no allocation allowed)
__device__ float g_bufA[MAXN * H];   // h (aggregate output / gemm input)
__device__ float g_bufB[MAXN * H];   // g = (h@W)*dis (gemm output / aggregate input)
__device__ float g_dis[MAXN];
__device__ int   g_deg[MAXN];
__device__ int   g_rowstart[MAXN + 1];
__device__ int   g_cursor[MAXN];
__device__ int   g_csrsrc[MAXE];
__device__ int   g_bsums[256];
__device__ float g_pool[128 * H];
__device__ float g_cnt[128];
__device__ int   g_flag;             // 1 if indices are int64, 0 if int32

__device__ __forceinline__ int getIdx(const void* p, long long i, int flag64) {
    if (flag64) return (int)((const long long*)p)[i];
    return ((const int*)p)[i];
}

// --- dtype detection: int64 little-endian => odd 32-bit words are 0 ----------
__global__ void detect_kernel(const void* ei) {
    const unsigned int* w = (const unsigned int*)ei;
    int is64 = 1;
    for (int i = 0; i < 64; i++) {
        if (w[2 * i + 1] != 0u) { is64 = 0; break; }
    }
    g_flag = is64;
}

// --- zero deg / pool / cnt ---------------------------------------------------
__global__ void init_kernel(int N, int G) {
    int i = blockIdx.x * blockDim.x + threadIdx.x;
    if (i < N) g_deg[i] = 0;
    if (i < G * H) g_pool[i] = 0.f;
    if (i < G) g_cnt[i] = 0.f;
}

// --- in-degree histogram -----------------------------------------------------
__global__ void hist_kernel(const void* ei, int E) {
    int e = blockIdx.x * blockDim.x + threadIdx.x;
    if (e >= E) return;
    int flag = g_flag;
    int dst = getIdx(ei, (long long)E + e, flag);
    atomicAdd(&g_deg[dst], 1);
}

// --- 3-phase exclusive scan over g_deg -> g_rowstart -------------------------
__global__ void scan1_kernel(int N) {
    __shared__ int s[256];
    int tid = threadIdx.x;
    int i = blockIdx.x * 256 + tid;
    int v = (i < N) ? g_deg[i] : 0;
    s[tid] = v;
    __syncthreads();
    for (int off = 1; off < 256; off <<= 1) {
        int t = (tid >= off) ? s[tid - off] : 0;
        __syncthreads();
        s[tid] += t;
        __syncthreads();
    }
    if (i < N) g_rowstart[i] = s[tid] - v;      // exclusive within block
    if (tid == 255) g_bsums[blockIdx.x] = s[255];
}

__global__ void scan2_kernel(int nb) {
    __shared__ int s[256];
    int tid = threadIdx.x;
    int v = (tid < nb) ? g_bsums[tid] : 0;
    s[tid] = v;
    __syncthreads();
    for (int off = 1; off < 256; off <<= 1) {
        int t = (tid >= off) ? s[tid - off] : 0;
        __syncthreads();
        s[tid] += t;
        __syncthreads();
    }
    if (tid < nb) g_bsums[tid] = s[tid] - v;    // exclusive block offsets
}

__global__ void scan3_kernel(int N, int E) {
    int i = blockIdx.x * 256 + threadIdx.x;
    if (i < N) {
        int val = g_rowstart[i] + g_bsums[blockIdx.x];
        g_rowstart[i] = val;
        g_cursor[i] = val;
        g_dis[i] = rsqrtf((float)(g_deg[i] + 1));   // +1 = self loop
    }
    if (i == 0) g_rowstart[N] = E;
}

// --- CSR fill: bucket src by dst --------------------------------------------
__global__ void fill_kernel(const void* ei, int E) {
    int e = blockIdx.x * blockDim.x + threadIdx.x;
    if (e >= E) return;
    int flag = g_flag;
    int src = getIdx(ei, e, flag);
    int dst = getIdx(ei, (long long)E + e, flag);
    int pos = atomicAdd(&g_cursor[dst], 1);
    g_csrsrc[pos] = src;
}

// --- layer-1 projection: g = (x @ W1) * dis  (K=3) ---------------------------
__global__ void gemm1_kernel(const float* __restrict__ x,
                             const float* __restrict__ W1,
                             float* __restrict__ out, int N) {
    int t = blockIdx.x * blockDim.x + threadIdx.x;
    int n = t >> 5, lane = t & 31;
    if (n >= N) return;
    float x0 = x[n * 3 + 0], x1 = x[n * 3 + 1], x2 = x[n * 3 + 2];
    float d = g_dis[n];
    float4 w0 = ((const float4*)(W1 + 0 * H))[lane];
    float4 w1 = ((const float4*)(W1 + 1 * H))[lane];
    float4 w2 = ((const float4*)(W1 + 2 * H))[lane];
    float4 o;
    o.x = (x0 * w0.x + x1 * w1.x + x2 * w2.x) * d;
    o.y = (x0 * w0.y + x1 * w1.y + x2 * w2.y) * d;
    o.z = (x0 * w0.z + x1 * w1.z + x2 * w2.z) * d;
    o.w = (x0 * w0.w + x1 * w1.w + x2 * w2.w) * d;
    ((float4*)(out + (size_t)n * H))[lane] = o;
}

// --- 128x128 tiled fp32 GEMM, epilogue *dis:  out = (A @ W) * dis ------------
#define GEMM_LDA 132
#define GEMM_SMEM ((128 * GEMM_LDA + 128 * 128) * 4)

__global__ void gemm128_kernel(const float* __restrict__ A,
                               float* __restrict__ Out,
                               const float* __restrict__ W, int N) {
    extern __shared__ float sm[];
    float* As = sm;                   // transposed: As[k*GEMM_LDA + m]
    float* Ws = sm + 128 * GEMM_LDA;  // row-major:  Ws[k*128 + c]
    int tid = threadIdx.x;
    int m0 = blockIdx.x * 128;

    for (int i = tid; i < 128 * 128 / 4; i += 256)
        ((float4*)Ws)[i] = ((const float4*)W)[i];

    for (int i = tid; i < 128 * 128 / 4; i += 256) {
        int idx = i * 4;
        int m = idx >> 7;
        int k = idx & 127;
        int gm = m0 + m;
        float4 v = make_float4(0.f, 0.f, 0.f, 0.f);
        if (gm < N) v = *((const float4*)(A + (size_t)gm * H + k));
        As[(k + 0) * GEMM_LDA + m] = v.x;
        As[(k + 1) * GEMM_LDA + m] = v.y;
        As[(k + 2) * GEMM_LDA + m] = v.z;
        As[(k + 3) * GEMM_LDA + m] = v.w;
    }
    __syncthreads();

    int tx = tid & 15, ty = tid >> 4;
    int r0 = ty * 8, c0 = tx * 8;
    float acc[8][8];
#pragma unroll
    for (int i = 0; i < 8; i++)
#pragma unroll
        for (int j = 0; j < 8; j++) acc[i][j] = 0.f;

#pragma unroll 8
    for (int k = 0; k < 128; k++) {
        float a[8], b[8];
        *(float4*)&a[0] = *(float4*)&As[k * GEMM_LDA + r0];
        *(float4*)&a[4] = *(float4*)&As[k * GEMM_LDA + r0 + 4];
        *(float4*)&b[0] = *(float4*)&Ws[k * 128 + c0];
        *(float4*)&b[4] = *(float4*)&Ws[k * 128 + c0 + 4];
#pragma unroll
        for (int i = 0; i < 8; i++)
#pragma unroll
            for (int j = 0; j < 8; j++) acc[i][j] += a[i] * b[j];
    }

#pragma unroll
    for (int i = 0; i < 8; i++) {
        int gm = m0 + r0 + i;
        if (gm < N) {
            float d = g_dis[gm];
            float4 v0, v1;
            v0.x = acc[i][0] * d; v0.y = acc[i][1] * d;
            v0.z = acc[i][2] * d; v0.w = acc[i][3] * d;
            v1.x = acc[i][4] * d; v1.y = acc[i][5] * d;
            v1.z = acc[i][6] * d; v1.w = acc[i][7] * d;
            *((float4*)(Out + (size_t)gm * H + c0)) = v0;
            *((float4*)(Out + (size_t)gm * H + c0 + 4)) = v1;
        }
    }
}

// --- aggregation: h[v] = relu(dis[v]*(sum_{e:dst=v} g[src] + g[v]) + b) ------
__global__ void aggregate_kernel(const float* __restrict__ g,
                                 float* __restrict__ hout,
                                 const float* __restrict__ bias, int N) {
    int warp = (blockIdx.x * blockDim.x + threadIdx.x) >> 5;
    int lane = threadIdx.x & 31;
    if (warp >= N) return;
    int v = warp;
    int start = g_rowstart[v];
    int end = g_rowstart[v + 1];

    float ax = 0.f, ay = 0.f, az = 0.f, aw = 0.f;
    for (int j0 = start; j0 < end; j0 += 32) {
        int nn = min(32, end - j0);
        int s = (j0 + lane < end) ? g_csrsrc[j0 + lane] : 0;
        for (int i = 0; i < nn; i++) {
            int si = __shfl_sync(0xffffffffu, s, i);
            float4 m = ((const float4*)(g + (size_t)si * H))[lane];
            ax += m.x; ay += m.y; az += m.z; aw += m.w;
        }
    }
    float4 gv = ((const float4*)(g + (size_t)v * H))[lane];
    float dv = g_dis[v];
    float4 bv = ((const float4*)bias)[lane];
    float4 o;
    o.x = fmaxf(dv * (ax + gv.x) + bv.x, 0.f);
    o.y = fmaxf(dv * (ay + gv.y) + bv.y, 0.f);
    o.z = fmaxf(dv * (az + gv.z) + bv.z, 0.f);
    o.w = fmaxf(dv * (aw + gv.w) + bv.w, 0.f);
    ((float4*)(hout + (size_t)v * H))[lane] = o;
}

// --- global mean pool (hierarchical, batch is sorted) ------------------------
__device__ __forceinline__ void pool_flush(int cur, int sbase, int G, int lane,
                                           float ax, float ay, float az, float aw,
                                           float c, float* sacc, float* scnt) {
    if (cur < 0) return;
    int gl = cur - sbase;
    if (gl >= 0 && gl < GMAX) {
        atomicAdd(&sacc[gl * H + lane * 4 + 0], ax);
        atomicAdd(&sacc[gl * H + lane * 4 + 1], ay);
        atomicAdd(&sacc[gl * H + lane * 4 + 2], az);
        atomicAdd(&sacc[gl * H + lane * 4 + 3], aw);
        if (lane == 0) atomicAdd(&scnt[gl], c);
    } else if (cur < G) {
        atomicAdd(&g_pool[cur * H + lane * 4 + 0], ax);
        atomicAdd(&g_pool[cur * H + lane * 4 + 1], ay);
        atomicAdd(&g_pool[cur * H + lane * 4 + 2], az);
        atomicAdd(&g_pool[cur * H + lane * 4 + 3], aw);
        if (lane == 0) atomicAdd(&g_cnt[cur], c);
    }
}

__global__ void pool_kernel(const float* __restrict__ h, const void* batchp,
                            int N, int G) {
    __shared__ float sacc[GMAX * H];
    __shared__ float scnt[GMAX];
    int tid = threadIdx.x, warp = tid >> 5, lane = tid & 31;
    int flag = g_flag;
    for (int i = tid; i < GMAX * H; i += 256) sacc[i] = 0.f;
    if (tid < GMAX) scnt[tid] = 0.f;
    int n0 = blockIdx.x * 256;
    int sbase = getIdx(batchp, min(n0, N - 1), flag);
    __syncthreads();

    int nb = n0 + warp * 32;
    float ax = 0.f, ay = 0.f, az = 0.f, aw = 0.f, c = 0.f;
    int cur = -1;
    for (int i = 0; i < 32; i++) {
        int n = nb + i;
        if (n >= N) break;
        int gI = getIdx(batchp, n, flag);
        if (gI != cur) {
            pool_flush(cur, sbase, G, lane, ax, ay, az, aw, c, sacc, scnt);
            cur = gI; ax = ay = az = aw = 0.f; c = 0.f;
        }
        float4 v = ((const float4*)(h + (size_t)n * H))[lane];
        ax += v.x; ay += v.y; az += v.z; aw += v.w;
        c += 1.f;
    }
    pool_flush(cur, sbase, G, lane, ax, ay, az, aw, c, sacc, scnt);
    __syncthreads();

    for (int i = tid; i < GMAX * H; i += 256) {
        int gl = i >> 7;
        if (sbase + gl < G) {
            float val = sacc[i];
            if (val != 0.f) atomicAdd(&g_pool[(sbase + gl) * H + (i & 127)], val);
        }
    }
    if (tid < GMAX && sbase + tid < G && scnt[tid] != 0.f)
        atomicAdd(&g_cnt[sbase + tid], scnt[tid]);
}

// --- final: out[g][c] = (pool[g]/max(cnt,1)) . Wl[:,c] + bl[c] ---------------
__global__ void final_kernel(float* __restrict__ out,
                             const float* __restrict__ Wl,
                             const float* __restrict__ bl, int G, int C) {
    int g = threadIdx.x;
    int c = blockIdx.x;
    if (g >= G || c >= C) return;
    float inv = 1.f / fmaxf(g_cnt[g], 1.f);
    float acc = 0.f;
#pragma unroll 8
    for (int k = 0; k < H; k++) acc += g_pool[g * H + k] * Wl[k * C + c];
    out[g * C + c] = acc * inv + bl[c];
}

// ---------------------------------------------------------------------------
extern "C" void kernel_launch(void* const* d_in, const int* in_sizes, int n_in,
                              void* d_out, int out_size) {
    const float* x  = (const float*)d_in[0];
    const void*  ei = d_in[1];
    const void*  bt = d_in[2];
    const float* W1 = (const float*)d_in[3];
    const float* b1 = (const float*)d_in[4];
    const float* W2 = (const float*)d_in[5];
    const float* b2 = (const float*)d_in[6];
    const float* W3 = (const float*)d_in[7];
    const float* b3 = (const float*)d_in[8];
    const float* Wl = (const float*)d_in[9];
    const float* bl = (const float*)d_in[10];
    float* out = (float*)d_out;

    int N = in_sizes[0] / 3;
    int E = in_sizes[1] / 2;
    int C = 5;
    int G = out_size / C;
    if (N > MAXN) N = MAXN;
    if (E > MAXE) E = MAXE;

    cudaFuncSetAttribute(gemm128_kernel,
                         cudaFuncAttributeMaxDynamicSharedMemorySize, GEMM_SMEM);

    float *bufA, *bufB;
    cudaGetSymbolAddress((void**)&bufA, g_bufA);
    cudaGetSymbolAddress((void**)&bufB, g_bufB);

    int nbN = (N + 255) / 256;
    int nbE = (E + 255) / 256;

    detect_kernel<<<1, 1>>>(ei);
    init_kernel<<<nbN, 256>>>(N, G);
    hist_kernel<<<nbE, 256>>>(ei, E);
    scan1_kernel<<<nbN, 256>>>(N);
    scan2_kernel<<<1, 256>>>(nbN);
    scan3_kernel<<<nbN, 256>>>(N, E);
    fill_kernel<<<nbE, 256>>>(ei, E);

    // layer 1
    gemm1_kernel<<<(N * 32 + 255) / 256, 256>>>(x, W1, bufB, N);
    aggregate_kernel<<<(N + 7) / 8, 256>>>(bufB, bufA, b1, N);
    // layer 2
    gemm128_kernel<<<(N + 127) / 128, 256, GEMM_SMEM>>>(bufA, bufB, W2, N);
    aggregate_kernel<<<(N + 7) / 8, 256>>>(bufB, bufA, b2, N);
    // layer 3
    gemm128_kernel<<<(N + 127) / 128, 256, GEMM_SMEM>>>(bufA, bufB, W3, N);
    aggregate_kernel<<<(N + 7) / 8, 256>>>(bufB, bufA, b3, N);

    pool_kernel<<<nbN, 256>>>(bufA, bt, N, G);
    final_kernel<<<C, 128>>>(out, Wl, bl, G, C);
}

// round 2
// speedup vs baseline: 1.0926x; 1.0926x over previous
#include <cuda_runtime.h>
#include <cuda_bf16.h>
#include <math.h>

// ---------------------------------------------------------------------------
// GCN: 3x GCNConv(relu) + global_mean_pool + linear
// N=50000 nodes, E=600000 edges, HIDDEN=128, G=128 graphs, C=5 classes
// ---------------------------------------------------------------------------

#define MAXN 50000
#define MAXE 600000
#define H 128
#define GMAX 8

// scratch (device globals -- no allocation allowed)
__device__ float g_bufA[MAXN * H];   // h (aggregate output / gemm input)
__device__ float g_bufB[MAXN * H];   // g = (h@W)*dis (gemm output / aggregate input)
__device__ float4 g_gx[MAXN];        // {x0*dis, x1*dis, x2*dis, dis}
__device__ float g_dis[MAXN];
__device__ int   g_deg[MAXN];
__device__ int   g_rowstart[MAXN + 1];
__device__ int   g_cursor[MAXN];
__device__ int   g_csrsrc[MAXE];
__device__ int   g_bsums[256];
__device__ float g_pool[128 * H];
__device__ float g_cnt[128];
__device__ int   g_flag;             // 1 if indices are int64, 0 if int32

__device__ __forceinline__ int getIdx(const void* p, long long i, int flag64) {
    if (flag64) return (int)((const long long*)p)[i];
    return ((const int*)p)[i];
}

// --- packed fp32x2 helpers (FFMA2 path, Blackwell) ---------------------------
__device__ __forceinline__ unsigned long long pack2(float x) {
    unsigned long long r;
    asm("mov.b64 %0, {%1, %1};" : "=l"(r) : "f"(x));
    return r;
}
__device__ __forceinline__ void ffma2(unsigned long long& d,
                                      unsigned long long a,
                                      unsigned long long b) {
    asm("fma.rn.f32x2 %0, %1, %2, %3;" : "=l"(d) : "l"(a), "l"(b), "l"(d));
}
__device__ __forceinline__ void unpack2(unsigned long long v, float& lo, float& hi) {
    asm("mov.b64 {%0, %1}, %2;" : "=f"(lo), "=f"(hi) : "l"(v));
}

// --- dtype detection: int64 little-endian => odd 32-bit words are 0 ----------
__global__ void detect_kernel(const void* ei) {
    const unsigned int* w = (const unsigned int*)ei;
    int is64 = 1;
    for (int i = 0; i < 64; i++) {
        if (w[2 * i + 1] != 0u) { is64 = 0; break; }
    }
    g_flag = is64;
}

// --- zero deg / pool / cnt ---------------------------------------------------
__global__ void init_kernel(int N, int G) {
    int i = blockIdx.x * blockDim.x + threadIdx.x;
    if (i < N) g_deg[i] = 0;
    if (i < G * H) g_pool[i] = 0.f;
    if (i < G) g_cnt[i] = 0.f;
}

// --- in-degree histogram -----------------------------------------------------
__global__ void hist_kernel(const void* ei, int E) {
    int e = blockIdx.x * blockDim.x + threadIdx.x;
    if (e >= E) return;
    int flag = g_flag;
    int dst = getIdx(ei, (long long)E + e, flag);
    atomicAdd(&g_deg[dst], 1);
}

// --- scan stage A: per-block (1024 elems) sums -------------------------------
__global__ void scanA_kernel(int N) {
    __shared__ int ws[8];
    int tid = threadIdx.x, lane = tid & 31, warp = tid >> 5;
    int base = blockIdx.x * 1024 + tid * 4;
    int s = 0;
#pragma unroll
    for (int j = 0; j < 4; j++)
        if (base + j < N) s += g_deg[base + j];
#pragma unroll
    for (int off = 16; off > 0; off >>= 1)
        s += __shfl_xor_sync(0xffffffffu, s, off);
    if (lane == 0) ws[warp] = s;
    __syncthreads();
    if (tid == 0) {
        int t = 0;
#pragma unroll
        for (int i = 0; i < 8; i++) t += ws[i];
        g_bsums[blockIdx.x] = t;
    }
}

// --- scan stage B: exclusive scan of block sums (nb <= 256) ------------------
__global__ void scanB_kernel(int nb) {
    __shared__ int s[256];
    int tid = threadIdx.x;
    int v = (tid < nb) ? g_bsums[tid] : 0;
    s[tid] = v;
    __syncthreads();
    for (int off = 1; off < 256; off <<= 1) {
        int t = (tid >= off) ? s[tid - off] : 0;
        __syncthreads();
        s[tid] += t;
        __syncthreads();
    }
    if (tid < nb) g_bsums[tid] = s[tid] - v;
}

// --- scan stage C: apply offsets, write rowstart/cursor/dis/gx ---------------
__global__ void scanC_kernel(const float* __restrict__ x, int N, int E) {
    __shared__ int ws[8];
    int tid = threadIdx.x, lane = tid & 31, warp = tid >> 5;
    int base = blockIdx.x * 1024 + tid * 4;
    int vals[4];
    int tsum = 0;
#pragma unroll
    for (int j = 0; j < 4; j++) {
        vals[j] = (base + j < N) ? g_deg[base + j] : 0;
        tsum += vals[j];
    }
    // warp inclusive scan of tsum
    int incl = tsum;
#pragma unroll
    for (int off = 1; off < 32; off <<= 1) {
        int t = __shfl_up_sync(0xffffffffu, incl, off);
        if (lane >= off) incl += t;
    }
    if (lane == 31) ws[warp] = incl;
    __syncthreads();
    int wbase = 0;
    if (warp > 0) {
#pragma unroll
        for (int i = 0; i < 7; i++) if (i < warp) wbase += ws[i];
    }
    int offset = g_bsums[blockIdx.x] + wbase + (incl - tsum);
#pragma unroll
    for (int j = 0; j < 4; j++) {
        int idx = base + j;
        if (idx < N) {
            g_rowstart[idx] = offset;
            g_cursor[idx] = offset;
            float d = rsqrtf((float)(vals[j] + 1));   // +1 = self loop
            g_dis[idx] = d;
            float4 gx;
            gx.x = x[idx * 3 + 0] * d;
            gx.y = x[idx * 3 + 1] * d;
            gx.z = x[idx * 3 + 2] * d;
            gx.w = d;
            g_gx[idx] = gx;
        }
        offset += vals[j];
    }
    if (blockIdx.x == 0 && tid == 0) g_rowstart[N] = E;
}

// --- CSR fill: bucket src by dst --------------------------------------------
__global__ void fill_kernel(const void* ei, int E) {
    int e = blockIdx.x * blockDim.x + threadIdx.x;
    if (e >= E) return;
    int flag = g_flag;
    int src = getIdx(ei, e, flag);
    int dst = getIdx(ei, (long long)E + e, flag);
    int pos = atomicAdd(&g_cursor[dst], 1);
    g_csrsrc[pos] = src;
}

// --- fused layer 1: h1 = relu( (A_hat X) @ W1 + b1 ), warp per node ----------
__global__ void layer1_kernel(const float* __restrict__ W1,
                              const float* __restrict__ b1,
                              float* __restrict__ hout, int N) {
    int warp = (blockIdx.x * blockDim.x + threadIdx.x) >> 5;
    int lane = threadIdx.x & 31;
    if (warp >= N) return;
    int v = warp;
    int start = g_rowstart[v];
    int end = g_rowstart[v + 1];

    float ax = 0.f, ay = 0.f, az = 0.f;
    for (int e = start + lane; e < end; e += 32) {
        int s = g_csrsrc[e];
        float4 gx = g_gx[s];
        ax += gx.x; ay += gx.y; az += gx.z;
    }
#pragma unroll
    for (int off = 16; off > 0; off >>= 1) {
        ax += __shfl_xor_sync(0xffffffffu, ax, off);
        ay += __shfl_xor_sync(0xffffffffu, ay, off);
        az += __shfl_xor_sync(0xffffffffu, az, off);
    }
    float4 self = g_gx[v];
    float d = self.w;
    float s0 = d * (ax + self.x);
    float s1 = d * (ay + self.y);
    float s2 = d * (az + self.z);

    float4 w0 = ((const float4*)(W1 + 0 * H))[lane];
    float4 w1 = ((const float4*)(W1 + 1 * H))[lane];
    float4 w2 = ((const float4*)(W1 + 2 * H))[lane];
    float4 bv = ((const float4*)b1)[lane];
    float4 o;
    o.x = fmaxf(s0 * w0.x + s1 * w1.x + s2 * w2.x + bv.x, 0.f);
    o.y = fmaxf(s0 * w0.y + s1 * w1.y + s2 * w2.y + bv.y, 0.f);
    o.z = fmaxf(s0 * w0.z + s1 * w1.z + s2 * w2.z + bv.z, 0.f);
    o.w = fmaxf(s0 * w0.w + s1 * w1.w + s2 * w2.w + bv.w, 0.f);
    ((float4*)(hout + (size_t)v * H))[lane] = o;
}

// --- 128x128 tiled fp32 GEMM (packed f32x2), epilogue *dis -------------------
#define GEMM_LDA 132
#define GEMM_SMEM ((128 * GEMM_LDA + 128 * 128) * 4)

__global__ void gemm128_kernel(const float* __restrict__ A,
                               float* __restrict__ Out,
                               const float* __restrict__ W, int N) {
    extern __shared__ float sm[];
    float* As = sm;                   // transposed: As[k*GEMM_LDA + m]
    float* Ws = sm + 128 * GEMM_LDA;  // row-major:  Ws[k*128 + c]
    int tid = threadIdx.x;
    int m0 = blockIdx.x * 128;

    for (int i = tid; i < 128 * 128 / 4; i += 256)
        ((float4*)Ws)[i] = ((const float4*)W)[i];

    for (int i = tid; i < 128 * 128 / 4; i += 256) {
        int idx = i * 4;
        int m = idx >> 7;
        int k = idx & 127;
        int gm = m0 + m;
        float4 v = make_float4(0.f, 0.f, 0.f, 0.f);
        if (gm < N) v = *((const float4*)(A + (size_t)gm * H + k));
        As[(k + 0) * GEMM_LDA + m] = v.x;
        As[(k + 1) * GEMM_LDA + m] = v.y;
        As[(k + 2) * GEMM_LDA + m] = v.z;
        As[(k + 3) * GEMM_LDA + m] = v.w;
    }
    __syncthreads();

    int tx = tid & 15, ty = tid >> 4;
    int r0 = ty * 8, c0 = tx * 8;
    unsigned long long acc[8][4];
#pragma unroll
    for (int i = 0; i < 8; i++)
#pragma unroll
        for (int j = 0; j < 4; j++) acc[i][j] = 0ull;

#pragma unroll 4
    for (int k = 0; k < 128; k++) {
        float4 a0 = *(const float4*)&As[k * GEMM_LDA + r0];
        float4 a1 = *(const float4*)&As[k * GEMM_LDA + r0 + 4];
        ulonglong2 bq0 = *(const ulonglong2*)&Ws[k * 128 + c0];
        ulonglong2 bq1 = *(const ulonglong2*)&Ws[k * 128 + c0 + 4];
        unsigned long long bb0 = bq0.x, bb1 = bq0.y, bb2 = bq1.x, bb3 = bq1.y;
        float av[8] = {a0.x, a0.y, a0.z, a0.w, a1.x, a1.y, a1.z, a1.w};
#pragma unroll
        for (int i = 0; i < 8; i++) {
            unsigned long long ai = pack2(av[i]);
            ffma2(acc[i][0], ai, bb0);
            ffma2(acc[i][1], ai, bb1);
            ffma2(acc[i][2], ai, bb2);
            ffma2(acc[i][3], ai, bb3);
        }
    }

#pragma unroll
    for (int i = 0; i < 8; i++) {
        int gm = m0 + r0 + i;
        if (gm < N) {
            float d = g_dis[gm];
            float o[8];
            unpack2(acc[i][0], o[0], o[1]);
            unpack2(acc[i][1], o[2], o[3]);
            unpack2(acc[i][2], o[4], o[5]);
            unpack2(acc[i][3], o[6], o[7]);
            float4 v0, v1;
            v0.x = o[0] * d; v0.y = o[1] * d; v0.z = o[2] * d; v0.w = o[3] * d;
            v1.x = o[4] * d; v1.y = o[5] * d; v1.z = o[6] * d; v1.w = o[7] * d;
            *((float4*)(Out + (size_t)gm * H + c0)) = v0;
            *((float4*)(Out + (size_t)gm * H + c0 + 4)) = v1;
        }
    }
}

// --- aggregation: h[v] = relu(dis[v]*(sum_{e:dst=v} g[src] + g[v]) + b) ------
__global__ void aggregate_kernel(const float* __restrict__ g,
                                 float* __restrict__ hout,
                                 const float* __restrict__ bias, int N) {
    int warp = (blockIdx.x * blockDim.x + threadIdx.x) >> 5;
    int lane = threadIdx.x & 31;
    if (warp >= N) return;
    int v = warp;
    int start = g_rowstart[v];
    int end = g_rowstart[v + 1];

    float ax = 0.f, ay = 0.f, az = 0.f, aw = 0.f;
    for (int j0 = start; j0 < end; j0 += 32) {
        int nn = min(32, end - j0);
        int s = (j0 + lane < end) ? g_csrsrc[j0 + lane] : 0;
        for (int i = 0; i < nn; i++) {
            int si = __shfl_sync(0xffffffffu, s, i);
            float4 m = ((const float4*)(g + (size_t)si * H))[lane];
            ax += m.x; ay += m.y; az += m.z; aw += m.w;
        }
    }
    float4 gv = ((const float4*)(g + (size_t)v * H))[lane];
    float dv = g_dis[v];
    float4 bv = ((const float4*)bias)[lane];
    float4 o;
    o.x = fmaxf(dv * (ax + gv.x) + bv.x, 0.f);
    o.y = fmaxf(dv * (ay + gv.y) + bv.y, 0.f);
    o.z = fmaxf(dv * (az + gv.z) + bv.z, 0.f);
    o.w = fmaxf(dv * (aw + gv.w) + bv.w, 0.f);
    ((float4*)(hout + (size_t)v * H))[lane] = o;
}

// --- global mean pool (hierarchical, batch is sorted) ------------------------
__device__ __forceinline__ void pool_flush(int cur, int sbase, int G, int lane,
                                           float ax, float ay, float az, float aw,
                                           float c, float* sacc, float* scnt) {
    if (cur < 0) return;
    int gl = cur - sbase;
    if (gl >= 0 && gl < GMAX) {
        atomicAdd(&sacc[gl * H + lane * 4 + 0], ax);
        atomicAdd(&sacc[gl * H + lane * 4 + 1], ay);
        atomicAdd(&sacc[gl * H + lane * 4 + 2], az);
        atomicAdd(&sacc[gl * H + lane * 4 + 3], aw);
        if (lane == 0) atomicAdd(&scnt[gl], c);
    } else if (cur < G) {
        atomicAdd(&g_pool[cur * H + lane * 4 + 0], ax);
        atomicAdd(&g_pool[cur * H + lane * 4 + 1], ay);
        atomicAdd(&g_pool[cur * H + lane * 4 + 2], az);
        atomicAdd(&g_pool[cur * H + lane * 4 + 3], aw);
        if (lane == 0) atomicAdd(&g_cnt[cur], c);
    }
}

__global__ void pool_kernel(const float* __restrict__ h, const void* batchp,
                            int N, int G) {
    __shared__ float sacc[GMAX * H];
    __shared__ float scnt[GMAX];
    int tid = threadIdx.x, warp = tid >> 5, lane = tid & 31;
    int flag = g_flag;
    for (int i = tid; i < GMAX * H; i += 256) sacc[i] = 0.f;
    if (tid < GMAX) scnt[tid] = 0.f;
    int n0 = blockIdx.x * 256;
    int sbase = getIdx(batchp, min(n0, N - 1), flag);
    __syncthreads();

    int nb = n0 + warp * 32;
    float ax = 0.f, ay = 0.f, az = 0.f, aw = 0.f, c = 0.f;
    int cur = -1;
    for (int i = 0; i < 32; i++) {
        int n = nb + i;
        if (n >= N) break;
        int gI = getIdx(batchp, n, flag);
        if (gI != cur) {
            pool_flush(cur, sbase, G, lane, ax, ay, az, aw, c, sacc, scnt);
            cur = gI; ax = ay = az = aw = 0.f; c = 0.f;
        }
        float4 v = ((const float4*)(h + (size_t)n * H))[lane];
        ax += v.x; ay += v.y; az += v.z; aw += v.w;
        c += 1.f;
    }
    pool_flush(cur, sbase, G, lane, ax, ay, az, aw, c, sacc, scnt);
    __syncthreads();

    for (int i = tid; i < GMAX * H; i += 256) {
        int gl = i >> 7;
        if (sbase + gl < G) {
            float val = sacc[i];
            if (val != 0.f) atomicAdd(&g_pool[(sbase + gl) * H + (i & 127)], val);
        }
    }
    if (tid < GMAX && sbase + tid < G && scnt[tid] != 0.f)
        atomicAdd(&g_cnt[sbase + tid], scnt[tid]);
}

// --- final: out[g][c] = (pool[g]/max(cnt,1)) . Wl[:,c] + bl[c] ---------------
__global__ void final_kernel(float* __restrict__ out,
                             const float* __restrict__ Wl,
                             const float* __restrict__ bl, int G, int C) {
    int g = threadIdx.x;
    int c = blockIdx.x;
    if (g >= G || c >= C) return;
    float inv = 1.f / fmaxf(g_cnt[g], 1.f);
    float acc = 0.f;
#pragma unroll 8
    for (int k = 0; k < H; k++) acc += g_pool[g * H + k] * Wl[k * C + c];
    out[g * C + c] = acc * inv + bl[c];
}

// ---------------------------------------------------------------------------
extern "C" void kernel_launch(void* const* d_in, const int* in_sizes, int n_in,
                              void* d_out, int out_size) {
    const float* x  = (const float*)d_in[0];
    const void*  ei = d_in[1];
    const void*  bt = d_in[2];
    const float* W1 = (const float*)d_in[3];
    const float* b1 = (const float*)d_in[4];
    const float* W2 = (const float*)d_in[5];
    const float* b2 = (const float*)d_in[6];
    const float* W3 = (const float*)d_in[7];
    const float* b3 = (const float*)d_in[8];
    const float* Wl = (const float*)d_in[9];
    const float* bl = (const float*)d_in[10];
    float* out = (float*)d_out;

    int N = in_sizes[0] / 3;
    int E = in_sizes[1] / 2;
    int C = 5;
    int G = out_size / C;
    if (N > MAXN) N = MAXN;
    if (E > MAXE) E = MAXE;

    cudaFuncSetAttribute(gemm128_kernel,
                         cudaFuncAttributeMaxDynamicSharedMemorySize, GEMM_SMEM);

    float *bufA, *bufB;
    cudaGetSymbolAddress((void**)&bufA, g_bufA);
    cudaGetSymbolAddress((void**)&bufB, g_bufB);

    int nbN = (N + 255) / 256;
    int nbE = (E + 255) / 256;
    int nbScan = (N + 1023) / 1024;     // <= 256

    detect_kernel<<<1, 1>>>(ei);
    init_kernel<<<nbN, 256>>>(N, G);
    hist_kernel<<<nbE, 256>>>(ei, E);
    scanA_kernel<<<nbScan, 256>>>(N);
    scanB_kernel<<<1, 256>>>(nbScan);
    scanC_kernel<<<nbScan, 256>>>(x, N, E);
    fill_kernel<<<nbE, 256>>>(ei, E);

    // layer 1 (fused aggregate-then-project)
    layer1_kernel<<<(N * 32 + 255) / 256, 256>>>(W1, b1, bufA, N);
    // layer 2
    gemm128_kernel<<<(N + 127) / 128, 256, GEMM_SMEM>>>(bufA, bufB, W2, N);
    aggregate_kernel<<<(N + 7) / 8, 256>>>(bufB, bufA, b2, N);
    // layer 3
    gemm128_kernel<<<(N + 127) / 128, 256, GEMM_SMEM>>>(bufA, bufB, W3, N);
    aggregate_kernel<<<(N + 7) / 8, 256>>>(bufB, bufA, b3, N);

    pool_kernel<<<nbN, 256>>>(bufA, bt, N, G);
    final_kernel<<<C, 128>>>(out, Wl, bl, G, C);
}

// round 5
// speedup vs baseline: 1.1194x; 1.0245x over previous
#include <cuda.h>
#include <cuda_runtime.h>
#include <cuda_bf16.h>
#include <cstdint>
#include <math.h>

// ---------------------------------------------------------------------------
// GCN: 3x GCNConv(relu) + global_mean_pool + linear
// N=50000, E=600000, HIDDEN=128, G=128, C=5
// GEMMs: warp-level mma.sync bf16 split (hi+lo), fp32 register accumulators.
// ---------------------------------------------------------------------------

#define MAXN 50000
#define MAXE 600000
#define H 128
#define GMAX 8

__device__ float g_bufA[MAXN * H];
__device__ float g_bufB[MAXN * H];
__device__ float4 g_gx[MAXN];        // {x0*dis, x1*dis, x2*dis, dis}
__device__ float g_dis[MAXN];
__device__ int   g_deg[MAXN];
__device__ int   g_rowstart[MAXN + 1];
__device__ int   g_cursor[MAXN];
__device__ int   g_csrsrc[MAXE];
__device__ int   g_bsums[256];
__device__ float g_pool[128 * H];
__device__ float g_cnt[128];
__device__ int   g_flag;             // 1 if indices are int64, 0 if int32

__device__ __forceinline__ int getIdx(const void* p, long long i, int flag64) {
    if (flag64) return (int)((const long long*)p)[i];
    return ((const int*)p)[i];
}

__device__ __forceinline__ uint32_t smem_u32(const void* p) {
    uint32_t a;
    asm("{ .reg .u64 t; cvta.to.shared.u64 t, %1; cvt.u32.u64 %0, t; }"
        : "=r"(a) : "l"(p));
    return a;
}

// ======================= mma.sync bf16 GEMM =================================
// Block: 64 rows x 128 cols. 8 warps = 2(m) x 4(n); warp tile 32x32.
// smem: A hi/lo [64][136] bf16, Wt hi/lo [128][136] bf16 (Wt[n][k]).

#define BM 64
#define APAD 136
#define S_AHI 0
#define S_ALO (BM * APAD * 2)                 // 17408
#define S_WHI (2 * BM * APAD * 2)             // 34816
#define S_WLO (S_WHI + 128 * APAD * 2)        // 69632
#define S_TOTAL (S_WLO + 128 * APAD * 2)      // 104448

__device__ __forceinline__ void ldsm4(uint32_t* r, uint32_t addr) {
    asm volatile("ldmatrix.sync.aligned.m8n8.x4.shared.b16 {%0,%1,%2,%3}, [%4];"
                 : "=r"(r[0]), "=r"(r[1]), "=r"(r[2]), "=r"(r[3]) : "r"(addr));
}
__device__ __forceinline__ void mma16816(float* c, const uint32_t* a,
                                         uint32_t b0, uint32_t b1) {
    asm volatile("mma.sync.aligned.m16n8k16.row.col.f32.bf16.bf16.f32 "
                 "{%0,%1,%2,%3}, {%4,%5,%6,%7}, {%8,%9}, {%0,%1,%2,%3};"
                 : "+f"(c[0]), "+f"(c[1]), "+f"(c[2]), "+f"(c[3])
                 : "r"(a[0]), "r"(a[1]), "r"(a[2]), "r"(a[3]), "r"(b0), "r"(b1));
}
__device__ __forceinline__ void split_pack(float x, float y,
                                           uint32_t& hp, uint32_t& lp) {
    __nv_bfloat16 hx = __float2bfloat16(x);
    __nv_bfloat16 hy = __float2bfloat16(y);
    __nv_bfloat16 lx = __float2bfloat16(x - __bfloat162float(hx));
    __nv_bfloat16 ly = __float2bfloat16(y - __bfloat162float(hy));
    hp = (uint32_t)__bfloat16_as_ushort(hx) | ((uint32_t)__bfloat16_as_ushort(hy) << 16);
    lp = (uint32_t)__bfloat16_as_ushort(lx) | ((uint32_t)__bfloat16_as_ushort(ly) << 16);
}

__global__ __launch_bounds__(256, 2)
void gemm_mma_kernel(const float* __restrict__ A,
                     float* __restrict__ Out,
                     const float* __restrict__ W, int N) {
    extern __shared__ char sm[];
    uint32_t sb = smem_u32(sm);
    int tid = threadIdx.x, wid = tid >> 5, lane = tid & 31;
    int m0 = blockIdx.x * BM;

    // ---- stage W: W[k][n] fp32 -> Wt[n][k] bf16 hi/lo (transposed) --------
#pragma unroll
    for (int i = 0; i < 8; i++) {
        int k0 = (i * 8 + wid) * 2;           // even k
        float4 va = *(const float4*)(W + (size_t)k0 * H + lane * 4);
        float4 vb = *(const float4*)(W + (size_t)(k0 + 1) * H + lane * 4);
        float ar[4] = {va.x, va.y, va.z, va.w};
        float br[4] = {vb.x, vb.y, vb.z, vb.w};
#pragma unroll
        for (int j = 0; j < 4; j++) {
            int n = lane * 4 + j;
            uint32_t hp, lp;
            split_pack(ar[j], br[j], hp, lp);  // (k0, k0+1) at row n
            *(uint32_t*)(sm + S_WHI + ((size_t)n * APAD + k0) * 2) = hp;
            *(uint32_t*)(sm + S_WLO + ((size_t)n * APAD + k0) * 2) = lp;
        }
    }
    // ---- stage A: A[m][k] fp32 -> As[m][k] bf16 hi/lo ---------------------
#pragma unroll
    for (int i = 0; i < 8; i++) {
        int m = i * 8 + wid;
        int gm = m0 + m;
        float4 v = make_float4(0.f, 0.f, 0.f, 0.f);
        if (gm < N) v = *(const float4*)(A + (size_t)gm * H + lane * 4);
        uint32_t hp01, lp01, hp23, lp23;
        split_pack(v.x, v.y, hp01, lp01);
        split_pack(v.z, v.w, hp23, lp23);
        size_t boff = ((size_t)m * APAD + lane * 4) * 2;
        *(uint32_t*)(sm + S_AHI + boff) = hp01;
        *(uint32_t*)(sm + S_AHI + boff + 4) = hp23;
        *(uint32_t*)(sm + S_ALO + boff) = lp01;
        *(uint32_t*)(sm + S_ALO + boff + 4) = lp23;
    }
    __syncthreads();

    int wm = wid & 1, wn = wid >> 1;
    float acc[2][4][4];
#pragma unroll
    for (int mi = 0; mi < 2; mi++)
#pragma unroll
        for (int ni = 0; ni < 4; ni++)
#pragma unroll
            for (int q = 0; q < 4; q++) acc[mi][ni][q] = 0.f;

    // per-lane ldmatrix base offsets
    int quad = lane >> 3, l7 = lane & 7;
    uint32_t aRow = (uint32_t)(wm * 32 + (quad & 1) * 8 + l7);
    uint32_t aK   = (uint32_t)((quad >> 1) * 8);
    uint32_t bN   = (uint32_t)(wn * 32 + (quad >> 1) * 8 + l7);
    uint32_t bK   = (uint32_t)((quad & 1) * 8);
    uint32_t aOff = (aRow * APAD + aK) * 2;
    uint32_t bOff = (bN * APAD + bK) * 2;

    const uint32_t aBase[3] = {S_AHI, S_ALO, S_AHI};
    const uint32_t wBase[3] = {S_WLO, S_WHI, S_WHI};

#pragma unroll
    for (int s = 0; s < 3; s++) {
        uint32_t aAddr = sb + aBase[s] + aOff;
        uint32_t bAddr = sb + wBase[s] + bOff;
#pragma unroll
        for (int k = 0; k < H; k += 16) {
            uint32_t a0[4], a1[4], b0[4], b1[4];
            ldsm4(a0, aAddr + k * 2);
            ldsm4(a1, aAddr + (16 * APAD) * 2 + k * 2);
            ldsm4(b0, bAddr + k * 2);
            ldsm4(b1, bAddr + (16 * APAD) * 2 + k * 2);
            mma16816(acc[0][0], a0, b0[0], b0[1]);
            mma16816(acc[0][1], a0, b0[2], b0[3]);
            mma16816(acc[0][2], a0, b1[0], b1[1]);
            mma16816(acc[0][3], a0, b1[2], b1[3]);
            mma16816(acc[1][0], a1, b0[0], b0[1]);
            mma16816(acc[1][1], a1, b0[2], b0[3]);
            mma16816(acc[1][2], a1, b1[0], b1[1]);
            mma16816(acc[1][3], a1, b1[2], b1[3]);
        }
    }

    // ---- epilogue: scale by dis[row], store ------------------------------
    int g = lane >> 2, tig = lane & 3;
#pragma unroll
    for (int mi = 0; mi < 2; mi++) {
        int row0 = m0 + wm * 32 + mi * 16 + g;
        int row1 = row0 + 8;
        float d0 = (row0 < N) ? g_dis[row0] : 0.f;
        float d1 = (row1 < N) ? g_dis[row1] : 0.f;
#pragma unroll
        for (int ni = 0; ni < 4; ni++) {
            int col = wn * 32 + ni * 8 + tig * 2;
            if (row0 < N) {
                float2 v = make_float2(acc[mi][ni][0] * d0, acc[mi][ni][1] * d0);
                *(float2*)(Out + (size_t)row0 * H + col) = v;
            }
            if (row1 < N) {
                float2 v = make_float2(acc[mi][ni][2] * d1, acc[mi][ni][3] * d1);
                *(float2*)(Out + (size_t)row1 * H + col) = v;
            }
        }
    }
}

// ======================= graph preprocessing ================================

__global__ void init_kernel(const void* ei, int N, int G) {
    int i = blockIdx.x * blockDim.x + threadIdx.x;
    if (i == 0) {
        const unsigned int* w = (const unsigned int*)ei;
        int is64 = 1;
        for (int j = 0; j < 64; j++)
            if (w[2 * j + 1] != 0u) { is64 = 0; break; }
        g_flag = is64;
    }
    if (i < N) g_deg[i] = 0;
    if (i < G * H) g_pool[i] = 0.f;
    if (i < G) g_cnt[i] = 0.f;
}

__global__ void hist_kernel(const void* ei, int E) {
    int e = blockIdx.x * blockDim.x + threadIdx.x;
    if (e >= E) return;
    int flag = g_flag;
    int dst = getIdx(ei, (long long)E + e, flag);
    atomicAdd(&g_deg[dst], 1);
}

__global__ void scanA_kernel(int N) {
    __shared__ int ws[8];
    int tid = threadIdx.x, lane = tid & 31, warp = tid >> 5;
    int base = blockIdx.x * 1024 + tid * 4;
    int s = 0;
#pragma unroll
    for (int j = 0; j < 4; j++)
        if (base + j < N) s += g_deg[base + j];
#pragma unroll
    for (int off = 16; off > 0; off >>= 1)
        s += __shfl_xor_sync(0xffffffffu, s, off);
    if (lane == 0) ws[warp] = s;
    __syncthreads();
    if (tid == 0) {
        int t = 0;
#pragma unroll
        for (int i = 0; i < 8; i++) t += ws[i];
        g_bsums[blockIdx.x] = t;
    }
}

__global__ void scanB_kernel(int nb) {
    __shared__ int s[256];
    int tid = threadIdx.x;
    int v = (tid < nb) ? g_bsums[tid] : 0;
    s[tid] = v;
    __syncthreads();
    for (int off = 1; off < 256; off <<= 1) {
        int t = (tid >= off) ? s[tid - off] : 0;
        __syncthreads();
        s[tid] += t;
        __syncthreads();
    }
    if (tid < nb) g_bsums[tid] = s[tid] - v;
}

__global__ void scanC_kernel(const float* __restrict__ x, int N, int E) {
    __shared__ int ws[8];
    int tid = threadIdx.x, lane = tid & 31, warp = tid >> 5;
    int base = blockIdx.x * 1024 + tid * 4;
    int vals[4];
    int tsum = 0;
#pragma unroll
    for (int j = 0; j < 4; j++) {
        vals[j] = (base + j < N) ? g_deg[base + j] : 0;
        tsum += vals[j];
    }
    int incl = tsum;
#pragma unroll
    for (int off = 1; off < 32; off <<= 1) {
        int t = __shfl_up_sync(0xffffffffu, incl, off);
        if (lane >= off) incl += t;
    }
    if (lane == 31) ws[warp] = incl;
    __syncthreads();
    int wbase = 0;
    if (warp > 0) {
#pragma unroll
        for (int i = 0; i < 7; i++) if (i < warp) wbase += ws[i];
    }
    int offset = g_bsums[blockIdx.x] + wbase + (incl - tsum);
#pragma unroll
    for (int j = 0; j < 4; j++) {
        int idx = base + j;
        if (idx < N) {
            g_rowstart[idx] = offset;
            g_cursor[idx] = offset;
            float d = rsqrtf((float)(vals[j] + 1));
            g_dis[idx] = d;
            float4 gx;
            gx.x = x[idx * 3 + 0] * d;
            gx.y = x[idx * 3 + 1] * d;
            gx.z = x[idx * 3 + 2] * d;
            gx.w = d;
            g_gx[idx] = gx;
        }
        offset += vals[j];
    }
    if (blockIdx.x == 0 && tid == 0) g_rowstart[N] = E;
}

__global__ void fill_kernel(const void* ei, int E) {
    int e = blockIdx.x * blockDim.x + threadIdx.x;
    if (e >= E) return;
    int flag = g_flag;
    int src = getIdx(ei, e, flag);
    int dst = getIdx(ei, (long long)E + e, flag);
    int pos = atomicAdd(&g_cursor[dst], 1);
    g_csrsrc[pos] = src;
}

// --- fused layer 1: h1 = relu( (A_hat X) @ W1 + b1 ), warp per node ----------
__global__ void layer1_kernel(const float* __restrict__ W1,
                              const float* __restrict__ b1,
                              float* __restrict__ hout, int N) {
    int warp = (blockIdx.x * blockDim.x + threadIdx.x) >> 5;
    int lane = threadIdx.x & 31;
    if (warp >= N) return;
    int v = warp;
    int start = g_rowstart[v];
    int end = g_rowstart[v + 1];

    float ax = 0.f, ay = 0.f, az = 0.f;
    for (int e = start + lane; e < end; e += 32) {
        int s = g_csrsrc[e];
        float4 gx = g_gx[s];
        ax += gx.x; ay += gx.y; az += gx.z;
    }
#pragma unroll
    for (int off = 16; off > 0; off >>= 1) {
        ax += __shfl_xor_sync(0xffffffffu, ax, off);
        ay += __shfl_xor_sync(0xffffffffu, ay, off);
        az += __shfl_xor_sync(0xffffffffu, az, off);
    }
    float4 self = g_gx[v];
    float d = self.w;
    float s0 = d * (ax + self.x);
    float s1 = d * (ay + self.y);
    float s2 = d * (az + self.z);

    float4 w0 = ((const float4*)(W1 + 0 * H))[lane];
    float4 w1 = ((const float4*)(W1 + 1 * H))[lane];
    float4 w2 = ((const float4*)(W1 + 2 * H))[lane];
    float4 bv = ((const float4*)b1)[lane];
    float4 o;
    o.x = fmaxf(s0 * w0.x + s1 * w1.x + s2 * w2.x + bv.x, 0.f);
    o.y = fmaxf(s0 * w0.y + s1 * w1.y + s2 * w2.y + bv.y, 0.f);
    o.z = fmaxf(s0 * w0.z + s1 * w1.z + s2 * w2.z + bv.z, 0.f);
    o.w = fmaxf(s0 * w0.w + s1 * w1.w + s2 * w2.w + bv.w, 0.f);
    ((float4*)(hout + (size_t)v * H))[lane] = o;
}

// --- aggregation: h[v] = relu(dis[v]*(sum_{e:dst=v} g[src] + g[v]) + b) ------
__global__ void aggregate_kernel(const float* __restrict__ g,
                                 float* __restrict__ hout,
                                 const float* __restrict__ bias, int N) {
    int warp = (blockIdx.x * blockDim.x + threadIdx.x) >> 5;
    int lane = threadIdx.x & 31;
    if (warp >= N) return;
    int v = warp;
    int start = g_rowstart[v];
    int end = g_rowstart[v + 1];

    float ax = 0.f, ay = 0.f, az = 0.f, aw = 0.f;
    for (int j0 = start; j0 < end; j0 += 32) {
        int nn = min(32, end - j0);
        int s = (j0 + lane < end) ? g_csrsrc[j0 + lane] : 0;
        for (int i = 0; i < nn; i++) {
            int si = __shfl_sync(0xffffffffu, s, i);
            float4 m = ((const float4*)(g + (size_t)si * H))[lane];
            ax += m.x; ay += m.y; az += m.z; aw += m.w;
        }
    }
    float4 gv = ((const float4*)(g + (size_t)v * H))[lane];
    float dv = g_dis[v];
    float4 bv = ((const float4*)bias)[lane];
    float4 o;
    o.x = fmaxf(dv * (ax + gv.x) + bv.x, 0.f);
    o.y = fmaxf(dv * (ay + gv.y) + bv.y, 0.f);
    o.z = fmaxf(dv * (az + gv.z) + bv.z, 0.f);
    o.w = fmaxf(dv * (aw + gv.w) + bv.w, 0.f);
    ((float4*)(hout + (size_t)v * H))[lane] = o;
}

// --- global mean pool (hierarchical, batch is sorted) ------------------------
__device__ __forceinline__ void pool_flush(int cur, int sbase, int G, int lane,
                                           float ax, float ay, float az, float aw,
                                           float c, float* sacc, float* scnt) {
    if (cur < 0) return;
    int gl = cur - sbase;
    if (gl >= 0 && gl < GMAX) {
        atomicAdd(&sacc[gl * H + lane * 4 + 0], ax);
        atomicAdd(&sacc[gl * H + lane * 4 + 1], ay);
        atomicAdd(&sacc[gl * H + lane * 4 + 2], az);
        atomicAdd(&sacc[gl * H + lane * 4 + 3], aw);
        if (lane == 0) atomicAdd(&scnt[gl], c);
    } else if (cur < G) {
        atomicAdd(&g_pool[cur * H + lane * 4 + 0], ax);
        atomicAdd(&g_pool[cur * H + lane * 4 + 1], ay);
        atomicAdd(&g_pool[cur * H + lane * 4 + 2], az);
        atomicAdd(&g_pool[cur * H + lane * 4 + 3], aw);
        if (lane == 0) atomicAdd(&g_cnt[cur], c);
    }
}

__global__ void pool_kernel(const float* __restrict__ h, const void* batchp,
                            int N, int G) {
    __shared__ float sacc[GMAX * H];
    __shared__ float scnt[GMAX];
    int tid = threadIdx.x, warp = tid >> 5, lane = tid & 31;
    int flag = g_flag;
    for (int i = tid; i < GMAX * H; i += 256) sacc[i] = 0.f;
    if (tid < GMAX) scnt[tid] = 0.f;
    int n0 = blockIdx.x * 256;
    int sbase = getIdx(batchp, min(n0, N - 1), flag);
    __syncthreads();

    int nb = n0 + warp * 32;
    float ax = 0.f, ay = 0.f, az = 0.f, aw = 0.f, c = 0.f;
    int cur = -1;
    for (int i = 0; i < 32; i++) {
        int n = nb + i;
        if (n >= N) break;
        int gI = getIdx(batchp, n, flag);
        if (gI != cur) {
            pool_flush(cur, sbase, G, lane, ax, ay, az, aw, c, sacc, scnt);
            cur = gI; ax = ay = az = aw = 0.f; c = 0.f;
        }
        float4 v = ((const float4*)(h + (size_t)n * H))[lane];
        ax += v.x; ay += v.y; az += v.z; aw += v.w;
        c += 1.f;
    }
    pool_flush(cur, sbase, G, lane, ax, ay, az, aw, c, sacc, scnt);
    __syncthreads();

    for (int i = tid; i < GMAX * H; i += 256) {
        int gl = i >> 7;
        if (sbase + gl < G) {
            float val = sacc[i];
            if (val != 0.f) atomicAdd(&g_pool[(sbase + gl) * H + (i & 127)], val);
        }
    }
    if (tid < GMAX && sbase + tid < G && scnt[tid] != 0.f)
        atomicAdd(&g_cnt[sbase + tid], scnt[tid]);
}

__global__ void final_kernel(float* __restrict__ out,
                             const float* __restrict__ Wl,
                             const float* __restrict__ bl, int G, int C) {
    int g = threadIdx.x;
    int c = blockIdx.x;
    if (g >= G || c >= C) return;
    float inv = 1.f / fmaxf(g_cnt[g], 1.f);
    float acc = 0.f;
#pragma unroll 8
    for (int k = 0; k < H; k++) acc += g_pool[g * H + k] * Wl[k * C + c];
    out[g * C + c] = acc * inv + bl[c];
}

// ---------------------------------------------------------------------------
extern "C" void kernel_launch(void* const* d_in, const int* in_sizes, int n_in,
                              void* d_out, int out_size) {
    const float* x  = (const float*)d_in[0];
    const void*  ei = d_in[1];
    const void*  bt = d_in[2];
    const float* W1 = (const float*)d_in[3];
    const float* b1 = (const float*)d_in[4];
    const float* W2 = (const float*)d_in[5];
    const float* b2 = (const float*)d_in[6];
    const float* W3 = (const float*)d_in[7];
    const float* b3 = (const float*)d_in[8];
    const float* Wl = (const float*)d_in[9];
    const float* bl = (const float*)d_in[10];
    float* out = (float*)d_out;

    int N = in_sizes[0] / 3;
    int E = in_sizes[1] / 2;
    int C = 5;
    int G = out_size / C;
    if (N > MAXN) N = MAXN;
    if (E > MAXE) E = MAXE;

    cudaFuncSetAttribute(gemm_mma_kernel,
                         cudaFuncAttributeMaxDynamicSharedMemorySize, S_TOTAL);

    float *bufA, *bufB;
    cudaGetSymbolAddress((void**)&bufA, g_bufA);
    cudaGetSymbolAddress((void**)&bufB, g_bufB);

    int nbN = (N + 255) / 256;
    int nbE = (E + 255) / 256;
    int nbScan = (N + 1023) / 1024;
    int nbTile = (N + BM - 1) / BM;

    init_kernel<<<nbN, 256>>>(ei, N, G);
    hist_kernel<<<nbE, 256>>>(ei, E);
    scanA_kernel<<<nbScan, 256>>>(N);
    scanB_kernel<<<1, 256>>>(nbScan);
    scanC_kernel<<<nbScan, 256>>>(x, N, E);
    fill_kernel<<<nbE, 256>>>(ei, E);

    // layer 1 (fused aggregate-then-project)
    layer1_kernel<<<(N * 32 + 255) / 256, 256>>>(W1, b1, bufA, N);
    // layer 2
    gemm_mma_kernel<<<nbTile, 256, S_TOTAL>>>(bufA, bufB, W2, N);
    aggregate_kernel<<<(N + 7) / 8, 256>>>(bufB, bufA, b2, N);
    // layer 3
    gemm_mma_kernel<<<nbTile, 256, S_TOTAL>>>(bufA, bufB, W3, N);
    aggregate_kernel<<<(N + 7) / 8, 256>>>(bufB, bufA, b3, N);

    pool_kernel<<<nbN, 256>>>(bufA, bt, N, G);
    final_kernel<<<C, 128>>>(out, Wl, bl, G, C);
}

// round 6
// speedup vs baseline: 1.1324x; 1.0116x over previous
#include <cuda.h>
#include <cuda_runtime.h>
#include <cuda_bf16.h>
#include <cstdint>
#include <math.h>

// ---------------------------------------------------------------------------
// GCN: 3x GCNConv(relu) + global_mean_pool + linear   (6-kernel pipeline)
//   hist -> scan(lookback) -> fill -> gemm2f(layer1+gemm2)
//        -> gemm3f(agg2+gemm3) -> poolf(agg3+pool+final)
// GEMMs: mma.sync bf16 split (hi+lo), fp32 accumulators.
// ---------------------------------------------------------------------------

#define MAXN 50000
#define MAXE 600000
#define H 128
#define GMAX 8
#define C 5

__device__ float g_bufB[MAXN * H];   // g2
__device__ float g_bufA[MAXN * H];   // g3
__device__ float4 g_gx[MAXN];        // {x0*dis, x1*dis, x2*dis, dis}
__device__ float g_dis[MAXN];
__device__ int   g_deg[MAXN];        // zeroed by poolf for next run
__device__ int   g_rowstart[MAXN + 1];
__device__ int   g_cursor[MAXN];
__device__ int   g_csrsrc[MAXE];
__device__ int   g_btotal[256];
__device__ int   g_sflag[256];       // zeroed by hist each run
__device__ float g_pool[128 * H];    // zeroed by poolf last block
__device__ float g_cnt[128];
__device__ int   g_done;

// all-threads-of-warp collective: 1 if indices are int64 (odd words of first
// 64 slots all zero), 0 if int32.
__device__ __forceinline__ int detect64(const void* p) {
    const unsigned int* w = (const unsigned int*)p;
    int lane = threadIdx.x & 31;
    unsigned int a = w[2 * lane + 1] | w[2 * (lane + 32) + 1];
    unsigned int nz = __ballot_sync(0xffffffffu, a != 0u);
    return nz == 0u;
}
__device__ __forceinline__ int getIdx(const void* p, long long i, int flag64) {
    if (flag64) return (int)((const long long*)p)[i];
    return ((const int*)p)[i];
}
__device__ __forceinline__ uint32_t smem_u32(const void* p) {
    uint32_t a;
    asm("{ .reg .u64 t; cvta.to.shared.u64 t, %1; cvt.u32.u64 %0, t; }"
        : "=r"(a) : "l"(p));
    return a;
}

// ======================= mma.sync bf16 GEMM core ============================
// Block: 128 rows x 128 cols, 512 thr, 16 warps (4m x 4n), warp tile 32x32.
#define APAD 136
#define S_AHI 0
#define S_ALO (128 * APAD * 2)            // 34816
#define S_WHI (2 * 128 * APAD * 2)        // 69632
#define S_WLO (S_WHI + 128 * APAD * 2)    // 104448
#define S_TOTAL (S_WLO + 128 * APAD * 2)  // 139264

__device__ __forceinline__ void ldsm4(uint32_t* r, uint32_t addr) {
    asm volatile("ldmatrix.sync.aligned.m8n8.x4.shared.b16 {%0,%1,%2,%3}, [%4];"
                 : "=r"(r[0]), "=r"(r[1]), "=r"(r[2]), "=r"(r[3]) : "r"(addr));
}
__device__ __forceinline__ void mma16816(float* c, const uint32_t* a,
                                         uint32_t b0, uint32_t b1) {
    asm volatile("mma.sync.aligned.m16n8k16.row.col.f32.bf16.bf16.f32 "
                 "{%0,%1,%2,%3}, {%4,%5,%6,%7}, {%8,%9}, {%0,%1,%2,%3};"
                 : "+f"(c[0]), "+f"(c[1]), "+f"(c[2]), "+f"(c[3])
                 : "r"(a[0]), "r"(a[1]), "r"(a[2]), "r"(a[3]), "r"(b0), "r"(b1));
}
__device__ __forceinline__ void split_pack(float x, float y,
                                           uint32_t& hp, uint32_t& lp) {
    __nv_bfloat16 hx = __float2bfloat16(x);
    __nv_bfloat16 hy = __float2bfloat16(y);
    __nv_bfloat16 lx = __float2bfloat16(x - __bfloat162float(hx));
    __nv_bfloat16 ly = __float2bfloat16(y - __bfloat162float(hy));
    hp = (uint32_t)__bfloat16_as_ushort(hx) | ((uint32_t)__bfloat16_as_ushort(hy) << 16);
    lp = (uint32_t)__bfloat16_as_ushort(lx) | ((uint32_t)__bfloat16_as_ushort(ly) << 16);
}

// stage W [k][n] fp32 -> Wt[n][k] bf16 hi/lo (transposed), 16 warps
__device__ __forceinline__ void stage_W(char* sm, const float* __restrict__ W,
                                        int wid, int lane) {
#pragma unroll
    for (int i = 0; i < 4; i++) {
        int k0 = (i * 16 + wid) * 2;
        float4 va = *(const float4*)(W + (size_t)k0 * H + lane * 4);
        float4 vb = *(const float4*)(W + (size_t)(k0 + 1) * H + lane * 4);
        float ar[4] = {va.x, va.y, va.z, va.w};
        float br[4] = {vb.x, vb.y, vb.z, vb.w};
#pragma unroll
        for (int j = 0; j < 4; j++) {
            int n = lane * 4 + j;
            uint32_t hp, lp;
            split_pack(ar[j], br[j], hp, lp);
            *(uint32_t*)(sm + S_WHI + ((size_t)n * APAD + k0) * 2) = hp;
            *(uint32_t*)(sm + S_WLO + ((size_t)n * APAD + k0) * 2) = lp;
        }
    }
}
__device__ __forceinline__ void store_Arow(char* sm, int r, int lane, float4 h) {
    uint32_t hp01, lp01, hp23, lp23;
    split_pack(h.x, h.y, hp01, lp01);
    split_pack(h.z, h.w, hp23, lp23);
    size_t boff = ((size_t)r * APAD + lane * 4) * 2;
    *(uint32_t*)(sm + S_AHI + boff) = hp01;
    *(uint32_t*)(sm + S_AHI + boff + 4) = hp23;
    *(uint32_t*)(sm + S_ALO + boff) = lp01;
    *(uint32_t*)(sm + S_ALO + boff + 4) = lp23;
}

// mainloop + epilogue (Out[row] *= g_dis[row])
__device__ __forceinline__ void mma_main(uint32_t sb, float* __restrict__ Out,
                                         int m0, int N, int wid, int lane) {
    int wm = wid & 3, wn = wid >> 2;
    float acc[2][4][4];
#pragma unroll
    for (int mi = 0; mi < 2; mi++)
#pragma unroll
        for (int ni = 0; ni < 4; ni++)
#pragma unroll
            for (int q = 0; q < 4; q++) acc[mi][ni][q] = 0.f;

    int quad = lane >> 3, l7 = lane & 7;
    uint32_t aRow = (uint32_t)(wm * 32 + (quad & 1) * 8 + l7);
    uint32_t aK   = (uint32_t)((quad >> 1) * 8);
    uint32_t bN   = (uint32_t)(wn * 32 + (quad >> 1) * 8 + l7);
    uint32_t bK   = (uint32_t)((quad & 1) * 8);
    uint32_t aOff = (aRow * APAD + aK) * 2;
    uint32_t bOff = (bN * APAD + bK) * 2;

    const uint32_t aBase[3] = {S_AHI, S_ALO, S_AHI};
    const uint32_t wBase[3] = {S_WLO, S_WHI, S_WHI};
#pragma unroll
    for (int s = 0; s < 3; s++) {
        uint32_t aAddr = sb + aBase[s] + aOff;
        uint32_t bAddr = sb + wBase[s] + bOff;
#pragma unroll
        for (int k = 0; k < H; k += 16) {
            uint32_t a0[4], a1[4], b0[4], b1[4];
            ldsm4(a0, aAddr + k * 2);
            ldsm4(a1, aAddr + (16 * APAD) * 2 + k * 2);
            ldsm4(b0, bAddr + k * 2);
            ldsm4(b1, bAddr + (16 * APAD) * 2 + k * 2);
            mma16816(acc[0][0], a0, b0[0], b0[1]);
            mma16816(acc[0][1], a0, b0[2], b0[3]);
            mma16816(acc[0][2], a0, b1[0], b1[1]);
            mma16816(acc[0][3], a0, b1[2], b1[3]);
            mma16816(acc[1][0], a1, b0[0], b0[1]);
            mma16816(acc[1][1], a1, b0[2], b0[3]);
            mma16816(acc[1][2], a1, b1[0], b1[1]);
            mma16816(acc[1][3], a1, b1[2], b1[3]);
        }
    }
    int g = lane >> 2, tig = lane & 3;
#pragma unroll
    for (int mi = 0; mi < 2; mi++) {
        int row0 = m0 + wm * 32 + mi * 16 + g;
        int row1 = row0 + 8;
        float d0 = (row0 < N) ? g_dis[row0] : 0.f;
        float d1 = (row1 < N) ? g_dis[row1] : 0.f;
#pragma unroll
        for (int ni = 0; ni < 4; ni++) {
            int col = wn * 32 + ni * 8 + tig * 2;
            if (row0 < N) {
                float2 v = make_float2(acc[mi][ni][0] * d0, acc[mi][ni][1] * d0);
                *(float2*)(Out + (size_t)row0 * H + col) = v;
            }
            if (row1 < N) {
                float2 v = make_float2(acc[mi][ni][2] * d1, acc[mi][ni][3] * d1);
                *(float2*)(Out + (size_t)row1 * H + col) = v;
            }
        }
    }
}

// --- gemm2f: layer1 (agg x -> project W1,b1,relu) fused as A-staging --------
__global__ __launch_bounds__(512, 1)
void gemm2f_kernel(const float* __restrict__ W1, const float* __restrict__ b1,
                   const float* __restrict__ W2, float* __restrict__ Out, int N) {
    extern __shared__ char sm[];
    uint32_t sb = smem_u32(sm);
    int tid = threadIdx.x, wid = tid >> 5, lane = tid & 31;
    int m0 = blockIdx.x * 128;

    stage_W(sm, W2, wid, lane);
#pragma unroll 1
    for (int j = 0; j < 8; j++) {
        int r = wid * 8 + j;
        int v = m0 + r;
        float4 h = make_float4(0.f, 0.f, 0.f, 0.f);
        if (v < N) {
            int start = g_rowstart[v], end = g_rowstart[v + 1];
            float ax = 0.f, ay = 0.f, az = 0.f;
            for (int e = start + lane; e < end; e += 32) {
                int s = g_csrsrc[e];
                float4 gx = g_gx[s];
                ax += gx.x; ay += gx.y; az += gx.z;
            }
#pragma unroll
            for (int off = 16; off > 0; off >>= 1) {
                ax += __shfl_xor_sync(0xffffffffu, ax, off);
                ay += __shfl_xor_sync(0xffffffffu, ay, off);
                az += __shfl_xor_sync(0xffffffffu, az, off);
            }
            float4 self = g_gx[v];
            float d = self.w;
            float s0 = d * (ax + self.x);
            float s1 = d * (ay + self.y);
            float s2 = d * (az + self.z);
            float4 w0 = ((const float4*)(W1 + 0 * H))[lane];
            float4 w1 = ((const float4*)(W1 + 1 * H))[lane];
            float4 w2 = ((const float4*)(W1 + 2 * H))[lane];
            float4 bv = ((const float4*)b1)[lane];
            h.x = fmaxf(s0 * w0.x + s1 * w1.x + s2 * w2.x + bv.x, 0.f);
            h.y = fmaxf(s0 * w0.y + s1 * w1.y + s2 * w2.y + bv.y, 0.f);
            h.z = fmaxf(s0 * w0.z + s1 * w1.z + s2 * w2.z + bv.z, 0.f);
            h.w = fmaxf(s0 * w0.w + s1 * w1.w + s2 * w2.w + bv.w, 0.f);
        }
        store_Arow(sm, r, lane, h);
    }
    __syncthreads();
    mma_main(sb, Out, m0, N, wid, lane);
}

// --- gemm3f: aggregate(g2)+relu fused as A-staging --------------------------
__global__ __launch_bounds__(512, 1)
void gemm3f_kernel(const float* __restrict__ b2, const float* __restrict__ W3,
                   const float* __restrict__ In, float* __restrict__ Out, int N) {
    extern __shared__ char sm[];
    uint32_t sb = smem_u32(sm);
    int tid = threadIdx.x, wid = tid >> 5, lane = tid & 31;
    int m0 = blockIdx.x * 128;

    stage_W(sm, W3, wid, lane);
#pragma unroll 1
    for (int j = 0; j < 8; j++) {
        int r = wid * 8 + j;
        int v = m0 + r;
        float4 h = make_float4(0.f, 0.f, 0.f, 0.f);
        if (v < N) {
            int start = g_rowstart[v], end = g_rowstart[v + 1];
            float4 a = make_float4(0.f, 0.f, 0.f, 0.f);
            for (int j0 = start; j0 < end; j0 += 32) {
                int nn = min(32, end - j0);
                int s = (j0 + lane < end) ? g_csrsrc[j0 + lane] : 0;
                for (int i = 0; i < nn; i++) {
                    int si = __shfl_sync(0xffffffffu, s, i);
                    float4 m = ((const float4*)(In + (size_t)si * H))[lane];
                    a.x += m.x; a.y += m.y; a.z += m.z; a.w += m.w;
                }
            }
            float4 gv = ((const float4*)(In + (size_t)v * H))[lane];
            float dv = g_dis[v];
            float4 bv = ((const float4*)b2)[lane];
            h.x = fmaxf(dv * (a.x + gv.x) + bv.x, 0.f);
            h.y = fmaxf(dv * (a.y + gv.y) + bv.y, 0.f);
            h.z = fmaxf(dv * (a.z + gv.z) + bv.z, 0.f);
            h.w = fmaxf(dv * (a.w + gv.w) + bv.w, 0.f);
        }
        store_Arow(sm, r, lane, h);
    }
    __syncthreads();
    mma_main(sb, Out, m0, N, wid, lane);
}

// ======================= graph preprocessing ================================

__global__ void hist_kernel(const void* ei, int E) {
    int flag = detect64(ei);
    int tid = threadIdx.x;
    if (blockIdx.x == 0) g_sflag[tid & 255] = 0;
    int e = blockIdx.x * blockDim.x + tid;
    if (e < E) {
        int dst = getIdx(ei, (long long)E + e, flag);
        atomicAdd(&g_deg[dst], 1);
    }
}

// single-pass exclusive scan with decoupled lookback (<=256 blocks, all resident)
__global__ void scan_kernel(const float* __restrict__ x, int N, int E) {
    __shared__ int ws[8];
    __shared__ int s_prev;
    int tid = threadIdx.x, lane = tid & 31, warp = tid >> 5;
    int bid = blockIdx.x;
    int base = bid * 1024 + tid * 4;
    int vals[4];
    int tsum = 0;
#pragma unroll
    for (int j = 0; j < 4; j++) {
        vals[j] = (base + j < N) ? g_deg[base + j] : 0;
        tsum += vals[j];
    }
    int incl = tsum;
#pragma unroll
    for (int off = 1; off < 32; off <<= 1) {
        int t = __shfl_up_sync(0xffffffffu, incl, off);
        if (lane >= off) incl += t;
    }
    if (lane == 31) ws[warp] = incl;
    __syncthreads();
    int wbase = 0, btot = 0;
#pragma unroll
    for (int i = 0; i < 8; i++) {
        int wv = ws[i];
        if (i < warp) wbase += wv;
        btot += wv;
    }
    if (tid == 0) {
        g_btotal[bid] = btot;
        __threadfence();
        ((volatile int*)g_sflag)[bid] = 1;
    }
    if (warp == 0) {
        int p = 0;
        for (int b = lane; b < bid; b += 32) {
            while (((volatile int*)g_sflag)[b] == 0) {}
            p += ((volatile int*)g_btotal)[b];
        }
#pragma unroll
        for (int off = 16; off > 0; off >>= 1)
            p += __shfl_xor_sync(0xffffffffu, p, off);
        if (lane == 0) s_prev = p;
    }
    __syncthreads();
    int offset = s_prev + wbase + (incl - tsum);
#pragma unroll
    for (int j = 0; j < 4; j++) {
        int idx = base + j;
        if (idx < N) {
            g_rowstart[idx] = offset;
            g_cursor[idx] = offset;
            float d = rsqrtf((float)(vals[j] + 1));
            g_dis[idx] = d;
            float4 gx;
            gx.x = x[idx * 3 + 0] * d;
            gx.y = x[idx * 3 + 1] * d;
            gx.z = x[idx * 3 + 2] * d;
            gx.w = d;
            g_gx[idx] = gx;
        }
        offset += vals[j];
    }
    if (bid == 0 && tid == 0) g_rowstart[N] = E;
}

__global__ void fill_kernel(const void* ei, int E) {
    int flag = detect64(ei);
    int e = blockIdx.x * blockDim.x + threadIdx.x;
    if (e >= E) return;
    int src = getIdx(ei, e, flag);
    int dst = getIdx(ei, (long long)E + e, flag);
    int pos = atomicAdd(&g_cursor[dst], 1);
    g_csrsrc[pos] = src;
}

// ======================= fused agg3 + pool + final ==========================
__device__ __forceinline__ void pool_flush(int cur, int sbase, int G, int lane,
                                           float4 a, float c,
                                           float* sacc, float* scnt) {
    if (cur < 0) return;
    int gl = cur - sbase;
    if (gl >= 0 && gl < GMAX) {
        atomicAdd(&sacc[gl * H + lane * 4 + 0], a.x);
        atomicAdd(&sacc[gl * H + lane * 4 + 1], a.y);
        atomicAdd(&sacc[gl * H + lane * 4 + 2], a.z);
        atomicAdd(&sacc[gl * H + lane * 4 + 3], a.w);
        if (lane == 0) atomicAdd(&scnt[gl], c);
    } else if (cur < G) {
        atomicAdd(&g_pool[cur * H + lane * 4 + 0], a.x);
        atomicAdd(&g_pool[cur * H + lane * 4 + 1], a.y);
        atomicAdd(&g_pool[cur * H + lane * 4 + 2], a.z);
        atomicAdd(&g_pool[cur * H + lane * 4 + 3], a.w);
        if (lane == 0) atomicAdd(&g_cnt[cur], c);
    }
}

__global__ void poolf_kernel(const float* __restrict__ g3,
                             const float* __restrict__ b3,
                             const void* batchp, const void* ei,
                             const float* __restrict__ Wl,
                             const float* __restrict__ bl,
                             float* __restrict__ out, int N, int G) {
    __shared__ float sacc[GMAX * H];
    __shared__ float scnt[GMAX];
    __shared__ int s_last;
    int tid = threadIdx.x, w = tid >> 5, lane = tid & 31;
    int flag = detect64(ei);   // batch shares dtype with edge_index
    int n0 = blockIdx.x * 128;

    for (int i = tid; i < GMAX * H; i += 256) sacc[i] = 0.f;
    if (tid < GMAX) scnt[tid] = 0.f;
    // zero deg slice for next run (deg unused after scan)
    for (int i = tid; i < 128; i += 256) {
        int v = n0 + i;
        if (v < N) g_deg[v] = 0;
    }
    int sbase = getIdx(batchp, min(n0, N - 1), flag);
    __syncthreads();

    float4 racc = make_float4(0.f, 0.f, 0.f, 0.f);
    float rc = 0.f;
    int cur = -1;
    float4 bv = ((const float4*)b3)[lane];
    for (int t = 0; t < 16; t++) {
        int v = n0 + w * 16 + t;
        if (v >= N) break;
        int gI = getIdx(batchp, v, flag);
        if (gI != cur) {
            pool_flush(cur, sbase, G, lane, racc, rc, sacc, scnt);
            cur = gI;
            racc = make_float4(0.f, 0.f, 0.f, 0.f);
            rc = 0.f;
        }
        // h3 row = relu(dis*(gather + self) + b3)
        float4 a = make_float4(0.f, 0.f, 0.f, 0.f);
        int start = g_rowstart[v], end = g_rowstart[v + 1];
        for (int j0 = start; j0 < end; j0 += 32) {
            int nn = min(32, end - j0);
            int s = (j0 + lane < end) ? g_csrsrc[j0 + lane] : 0;
            for (int i = 0; i < nn; i++) {
                int si = __shfl_sync(0xffffffffu, s, i);
                float4 m = ((const float4*)(g3 + (size_t)si * H))[lane];
                a.x += m.x; a.y += m.y; a.z += m.z; a.w += m.w;
            }
        }
        float4 gv = ((const float4*)(g3 + (size_t)v * H))[lane];
        float dv = g_dis[v];
        racc.x += fmaxf(dv * (a.x + gv.x) + bv.x, 0.f);
        racc.y += fmaxf(dv * (a.y + gv.y) + bv.y, 0.f);
        racc.z += fmaxf(dv * (a.z + gv.z) + bv.z, 0.f);
        racc.w += fmaxf(dv * (a.w + gv.w) + bv.w, 0.f);
        rc += 1.f;
    }
    pool_flush(cur, sbase, G, lane, racc, rc, sacc, scnt);
    __syncthreads();

    for (int i = tid; i < GMAX * H; i += 256) {
        int gl = i >> 7;
        if (sbase + gl < G) {
            float val = sacc[i];
            if (val != 0.f) atomicAdd(&g_pool[(sbase + gl) * H + (i & 127)], val);
        }
    }
    if (tid < GMAX && sbase + tid < G && scnt[tid] != 0.f)
        atomicAdd(&g_cnt[sbase + tid], scnt[tid]);

    // last-block: final linear + state re-zero for next replay
    __threadfence();
    if (tid == 0) s_last = atomicAdd(&g_done, 1);
    __syncthreads();
    if (s_last == (int)gridDim.x - 1) {
        for (int idx = tid; idx < G * C; idx += 256) {
            int g = idx / C, c = idx % C;
            float cnt = __ldcg(&g_cnt[g]);
            float inv = 1.f / fmaxf(cnt, 1.f);
            float acc = 0.f;
#pragma unroll 8
            for (int k = 0; k < H; k++)
                acc += __ldcg(&g_pool[g * H + k]) * Wl[k * C + c];
            out[idx] = acc * inv + bl[c];
        }
        __syncthreads();
        for (int idx = tid; idx < G * H; idx += 256) g_pool[idx] = 0.f;
        if (tid < G) g_cnt[tid] = 0.f;
        if (tid == 0) g_done = 0;
    }
}

// ---------------------------------------------------------------------------
extern "C" void kernel_launch(void* const* d_in, const int* in_sizes, int n_in,
                              void* d_out, int out_size) {
    const float* x  = (const float*)d_in[0];
    const void*  ei = d_in[1];
    const void*  bt = d_in[2];
    const float* W1 = (const float*)d_in[3];
    const float* b1 = (const float*)d_in[4];
    const float* W2 = (const float*)d_in[5];
    const float* b2 = (const float*)d_in[6];
    const float* W3 = (const float*)d_in[7];
    const float* b3 = (const float*)d_in[8];
    const float* Wl = (const float*)d_in[9];
    const float* bl = (const float*)d_in[10];
    float* out = (float*)d_out;

    int N = in_sizes[0] / 3;
    int E = in_sizes[1] / 2;
    int G = out_size / C;
    if (N > MAXN) N = MAXN;
    if (E > MAXE) E = MAXE;

    cudaFuncSetAttribute(gemm2f_kernel,
                         cudaFuncAttributeMaxDynamicSharedMemorySize, S_TOTAL);
    cudaFuncSetAttribute(gemm3f_kernel,
                         cudaFuncAttributeMaxDynamicSharedMemorySize, S_TOTAL);

    float *bufA, *bufB;
    cudaGetSymbolAddress((void**)&bufA, g_bufA);
    cudaGetSymbolAddress((void**)&bufB, g_bufB);

    int nbE = (E + 255) / 256;
    int nbScan = (N + 1023) / 1024;     // <= 256, all co-resident
    int nbTile = (N + 127) / 128;

    hist_kernel<<<nbE, 256>>>(ei, E);
    scan_kernel<<<nbScan, 256>>>(x, N, E);
    fill_kernel<<<nbE, 256>>>(ei, E);
    gemm2f_kernel<<<nbTile, 512, S_TOTAL>>>(W1, b1, W2, bufB, N);   // -> g2
    gemm3f_kernel<<<nbTile, 512, S_TOTAL>>>(b2, W3, bufB, bufA, N); // -> g3
    poolf_kernel<<<nbTile, 256>>>(bufA, b3, bt, ei, Wl, bl, out, N, G);
}

// round 8
// speedup vs baseline: 1.2331x; 1.0889x over previous
#include <cuda.h>
#include <cuda_runtime.h>
#include <cuda_bf16.h>
#include <cstdint>
#include <math.h>

// ---------------------------------------------------------------------------
// GCN: 3x GCNConv(relu) + global_mean_pool + linear   (7-kernel pipeline)
//   hist -> scan(lookback) -> fill -> wprep -> gemm2f -> gemm3f -> poolf
// GEMMs: mma.sync bf16 split (hi+lo), fp32 accumulators.
// W pre-converted once into fragment-ordered global bf16 hi/lo arrays.
// ---------------------------------------------------------------------------

#define MAXN 50000
#define MAXE 600000
#define H 128
#define GMAX 8
#define C 5

__device__ float g_bufB[MAXN * H];   // g2
__device__ float g_bufA[MAXN * H];   // g3
__device__ float4 g_gx[MAXN];        // {x0*dis, x1*dis, x2*dis, dis}
__device__ float g_dis[MAXN];
__device__ int   g_deg[MAXN];        // zeroed by poolf for next run
__device__ int   g_rowstart[MAXN + 1];
__device__ int   g_cursor[MAXN];
__device__ int   g_csrsrc[MAXE];
__device__ int   g_btotal[256];
__device__ int   g_sflag[256];       // zeroed by hist each run
__device__ float g_pool[128 * H];    // zeroed by poolf last block
__device__ float g_cnt[128];
__device__ int   g_done;
// W fragments: uint32 [16 nb][8 kb][32 lane][2 pair]
__device__ uint32_t g_w2hi[8192], g_w2lo[8192];
__device__ uint32_t g_w3hi[8192], g_w3lo[8192];

__device__ __forceinline__ int detect64(const void* p) {
    const unsigned int* w = (const unsigned int*)p;
    int lane = threadIdx.x & 31;
    unsigned int a = w[2 * lane + 1] | w[2 * (lane + 32) + 1];
    unsigned int nz = __ballot_sync(0xffffffffu, a != 0u);
    return nz == 0u;
}
__device__ __forceinline__ int getIdx(const void* p, long long i, int flag64) {
    if (flag64) return (int)((const long long*)p)[i];
    return ((const int*)p)[i];
}
__device__ __forceinline__ uint32_t smem_u32(const void* p) {
    uint32_t a;
    asm("{ .reg .u64 t; cvta.to.shared.u64 t, %1; cvt.u32.u64 %0, t; }"
        : "=r"(a) : "l"(p));
    return a;
}

// ======================= mma.sync bf16 GEMM core ============================
// Block: 64 rows x 128 cols, 256 thr, 8 warps (2m x 4n), warp tile 32x32.
// A hi/lo staged in smem; B (W) fragments loaded from global (L1-resident).
#define APAD 136
#define S_AHI 0
#define S_ALO (64 * APAD * 2)            // 17408
#define S_TOTAL (2 * 64 * APAD * 2)      // 34816

__device__ __forceinline__ void ldsm4(uint32_t* r, uint32_t addr) {
    asm volatile("ldmatrix.sync.aligned.m8n8.x4.shared.b16 {%0,%1,%2,%3}, [%4];"
                 : "=r"(r[0]), "=r"(r[1]), "=r"(r[2]), "=r"(r[3]) : "r"(addr));
}
__device__ __forceinline__ void mma16816(float* c, const uint32_t* a,
                                         uint32_t b0, uint32_t b1) {
    asm volatile("mma.sync.aligned.m16n8k16.row.col.f32.bf16.bf16.f32 "
                 "{%0,%1,%2,%3}, {%4,%5,%6,%7}, {%8,%9}, {%0,%1,%2,%3};"
                 : "+f"(c[0]), "+f"(c[1]), "+f"(c[2]), "+f"(c[3])
                 : "r"(a[0]), "r"(a[1]), "r"(a[2]), "r"(a[3]), "r"(b0), "r"(b1));
}
__device__ __forceinline__ void split_pack(float x, float y,
                                           uint32_t& hp, uint32_t& lp) {
    __nv_bfloat16 hx = __float2bfloat16(x);
    __nv_bfloat16 hy = __float2bfloat16(y);
    __nv_bfloat16 lx = __float2bfloat16(x - __bfloat162float(hx));
    __nv_bfloat16 ly = __float2bfloat16(y - __bfloat162float(hy));
    hp = (uint32_t)__bfloat16_as_ushort(hx) | ((uint32_t)__bfloat16_as_ushort(hy) << 16);
    lp = (uint32_t)__bfloat16_as_ushort(lx) | ((uint32_t)__bfloat16_as_ushort(ly) << 16);
}
__device__ __forceinline__ void store_Arow(char* sm, int r, int lane, float4 h) {
    uint32_t hp01, lp01, hp23, lp23;
    split_pack(h.x, h.y, hp01, lp01);
    split_pack(h.z, h.w, hp23, lp23);
    size_t boff = ((size_t)r * APAD + lane * 4) * 2;   // 8B aligned
    *(uint2*)(sm + S_AHI + boff) = make_uint2(hp01, hp23);
    *(uint2*)(sm + S_ALO + boff) = make_uint2(lp01, lp23);
}

// --- wprep: W[k][n] fp32 -> fragment-ordered bf16 hi/lo ---------------------
// frag index i: nb = i>>9, kb = (i>>6)&7, lane = (i>>1)&31, pair = i&1
// value = pack(W[k][n], W[k+1][n]); n = nb*8 + lane/4, k = kb*16 + (lane&3)*2 + pair*8
__global__ void wprep_kernel(const float* __restrict__ W2,
                             const float* __restrict__ W3) {
    int t = blockIdx.x * 256 + threadIdx.x;
    if (t >= 16384) return;
    const float* W = (t & 8192) ? W3 : W2;
    uint32_t* dhi = (t & 8192) ? g_w3hi : g_w2hi;
    uint32_t* dlo = (t & 8192) ? g_w3lo : g_w2lo;
    int i = t & 8191;
    int pair = i & 1;
    int lane = (i >> 1) & 31;
    int kb = (i >> 6) & 7;
    int nb = i >> 9;
    int n = nb * 8 + (lane >> 2);
    int k = kb * 16 + (lane & 3) * 2 + pair * 8;
    uint32_t hp, lp;
    split_pack(W[k * H + n], W[(k + 1) * H + n], hp, lp);
    dhi[i] = hp;
    dlo[i] = lp;
}

// mainloop + epilogue (Out[row] *= g_dis[row]); B from global fragments
__device__ __forceinline__ void mma_main(uint32_t sb,
                                         const uint32_t* __restrict__ whi,
                                         const uint32_t* __restrict__ wlo,
                                         float* __restrict__ Out,
                                         int m0, int N, int wid, int lane) {
    int wm = wid & 1, wn = wid >> 1;
    float acc[2][4][4];
#pragma unroll
    for (int mi = 0; mi < 2; mi++)
#pragma unroll
        for (int ni = 0; ni < 4; ni++)
#pragma unroll
            for (int q = 0; q < 4; q++) acc[mi][ni][q] = 0.f;

    int quad = lane >> 3, l7 = lane & 7;
    uint32_t aRow = (uint32_t)(wm * 32 + (quad & 1) * 8 + l7);
    uint32_t aK   = (uint32_t)((quad >> 1) * 8);
    uint32_t aOff = (aRow * APAD + aK) * 2;

    const uint32_t aBase[3] = {S_AHI, S_ALO, S_AHI};
    const uint32_t* wB[3] = {wlo, whi, whi};
#pragma unroll
    for (int s = 0; s < 3; s++) {
        uint32_t aAddr = sb + aBase[s] + aOff;
        const uint2* wb = (const uint2*)wB[s];
#pragma unroll
        for (int ks = 0; ks < 8; ks++) {
            uint32_t a0[4], a1[4];
            ldsm4(a0, aAddr + ks * 32);
            ldsm4(a1, aAddr + (16 * APAD) * 2 + ks * 32);
            uint2 b0 = wb[((wn * 4 + 0) * 8 + ks) * 32 + lane];
            uint2 b1 = wb[((wn * 4 + 1) * 8 + ks) * 32 + lane];
            uint2 b2 = wb[((wn * 4 + 2) * 8 + ks) * 32 + lane];
            uint2 b3 = wb[((wn * 4 + 3) * 8 + ks) * 32 + lane];
            mma16816(acc[0][0], a0, b0.x, b0.y);
            mma16816(acc[0][1], a0, b1.x, b1.y);
            mma16816(acc[0][2], a0, b2.x, b2.y);
            mma16816(acc[0][3], a0, b3.x, b3.y);
            mma16816(acc[1][0], a1, b0.x, b0.y);
            mma16816(acc[1][1], a1, b1.x, b1.y);
            mma16816(acc[1][2], a1, b2.x, b2.y);
            mma16816(acc[1][3], a1, b3.x, b3.y);
        }
    }
    int g = lane >> 2, tig = lane & 3;
#pragma unroll
    for (int mi = 0; mi < 2; mi++) {
        int row0 = m0 + wm * 32 + mi * 16 + g;
        int row1 = row0 + 8;
        float d0 = (row0 < N) ? g_dis[row0] : 0.f;
        float d1 = (row1 < N) ? g_dis[row1] : 0.f;
#pragma unroll
        for (int ni = 0; ni < 4; ni++) {
            int col = wn * 32 + ni * 8 + tig * 2;
            if (row0 < N) {
                float2 v = make_float2(acc[mi][ni][0] * d0, acc[mi][ni][1] * d0);
                *(float2*)(Out + (size_t)row0 * H + col) = v;
            }
            if (row1 < N) {
                float2 v = make_float2(acc[mi][ni][2] * d1, acc[mi][ni][3] * d1);
                *(float2*)(Out + (size_t)row1 * H + col) = v;
            }
        }
    }
}

// --- gemm2f: layer1 (agg x -> project W1,b1,relu) fused as A-staging --------
__global__ __launch_bounds__(256, 2)
void gemm2f_kernel(const float* __restrict__ W1, const float* __restrict__ b1,
                   float* __restrict__ Out, int N) {
    extern __shared__ char sm[];
    uint32_t sb = smem_u32(sm);
    int tid = threadIdx.x, wid = tid >> 5, lane = tid & 31;
    int m0 = blockIdx.x * 64;

#pragma unroll 1
    for (int j = 0; j < 8; j++) {
        int r = wid * 8 + j;
        int v = m0 + r;
        float4 h = make_float4(0.f, 0.f, 0.f, 0.f);
        if (v < N) {
            int start = g_rowstart[v], end = g_rowstart[v + 1];
            float ax = 0.f, ay = 0.f, az = 0.f;
            for (int e = start + lane; e < end; e += 32) {
                int s = g_csrsrc[e];
                float4 gx = g_gx[s];
                ax += gx.x; ay += gx.y; az += gx.z;
            }
#pragma unroll
            for (int off = 16; off > 0; off >>= 1) {
                ax += __shfl_xor_sync(0xffffffffu, ax, off);
                ay += __shfl_xor_sync(0xffffffffu, ay, off);
                az += __shfl_xor_sync(0xffffffffu, az, off);
            }
            float4 self = g_gx[v];
            float d = self.w;
            float s0 = d * (ax + self.x);
            float s1 = d * (ay + self.y);
            float s2 = d * (az + self.z);
            float4 w0 = ((const float4*)(W1 + 0 * H))[lane];
            float4 w1 = ((const float4*)(W1 + 1 * H))[lane];
            float4 w2 = ((const float4*)(W1 + 2 * H))[lane];
            float4 bv = ((const float4*)b1)[lane];
            h.x = fmaxf(s0 * w0.x + s1 * w1.x + s2 * w2.x + bv.x, 0.f);
            h.y = fmaxf(s0 * w0.y + s1 * w1.y + s2 * w2.y + bv.y, 0.f);
            h.z = fmaxf(s0 * w0.z + s1 * w1.z + s2 * w2.z + bv.z, 0.f);
            h.w = fmaxf(s0 * w0.w + s1 * w1.w + s2 * w2.w + bv.w, 0.f);
        }
        store_Arow(sm, r, lane, h);
    }
    __syncthreads();
    mma_main(sb, g_w2hi, g_w2lo, Out, m0, N, wid, lane);
}

// --- gemm3f: aggregate(g2)+relu fused as A-staging --------------------------
__global__ __launch_bounds__(256, 2)
void gemm3f_kernel(const float* __restrict__ b2, const float* __restrict__ In,
                   float* __restrict__ Out, int N) {
    extern __shared__ char sm[];
    uint32_t sb = smem_u32(sm);
    int tid = threadIdx.x, wid = tid >> 5, lane = tid & 31;
    int m0 = blockIdx.x * 64;

#pragma unroll 1
    for (int j = 0; j < 8; j++) {
        int r = wid * 8 + j;
        int v = m0 + r;
        float4 h = make_float4(0.f, 0.f, 0.f, 0.f);
        if (v < N) {
            int start = g_rowstart[v], end = g_rowstart[v + 1];
            float4 a = make_float4(0.f, 0.f, 0.f, 0.f);
            for (int j0 = start; j0 < end; j0 += 32) {
                int nn = min(32, end - j0);
                int s = (j0 + lane < end) ? g_csrsrc[j0 + lane] : 0;
                for (int i = 0; i < nn; i++) {
                    int si = __shfl_sync(0xffffffffu, s, i);
                    float4 m = ((const float4*)(In + (size_t)si * H))[lane];
                    a.x += m.x; a.y += m.y; a.z += m.z; a.w += m.w;
                }
            }
            float4 gv = ((const float4*)(In + (size_t)v * H))[lane];
            float dv = g_dis[v];
            float4 bv = ((const float4*)b2)[lane];
            h.x = fmaxf(dv * (a.x + gv.x) + bv.x, 0.f);
            h.y = fmaxf(dv * (a.y + gv.y) + bv.y, 0.f);
            h.z = fmaxf(dv * (a.z + gv.z) + bv.z, 0.f);
            h.w = fmaxf(dv * (a.w + gv.w) + bv.w, 0.f);
        }
        store_Arow(sm, r, lane, h);
    }
    __syncthreads();
    mma_main(sb, g_w3hi, g_w3lo, Out, m0, N, wid, lane);
}

// ======================= graph preprocessing ================================

__global__ void hist_kernel(const void* ei, int E) {
    int flag = detect64(ei);
    int tid = threadIdx.x;
    if (blockIdx.x == 0) g_sflag[tid & 255] = 0;
    int e = blockIdx.x * blockDim.x + tid;
    if (e < E) {
        int dst = getIdx(ei, (long long)E + e, flag);
        atomicAdd(&g_deg[dst], 1);
    }
}

__global__ void scan_kernel(const float* __restrict__ x, int N, int E) {
    __shared__ int ws[8];
    __shared__ int s_prev;
    int tid = threadIdx.x, lane = tid & 31, warp = tid >> 5;
    int bid = blockIdx.x;
    int base = bid * 1024 + tid * 4;
    int vals[4];
    int tsum = 0;
#pragma unroll
    for (int j = 0; j < 4; j++) {
        vals[j] = (base + j < N) ? g_deg[base + j] : 0;
        tsum += vals[j];
    }
    int incl = tsum;
#pragma unroll
    for (int off = 1; off < 32; off <<= 1) {
        int t = __shfl_up_sync(0xffffffffu, incl, off);
        if (lane >= off) incl += t;
    }
    if (lane == 31) ws[warp] = incl;
    __syncthreads();
    int wbase = 0, btot = 0;
#pragma unroll
    for (int i = 0; i < 8; i++) {
        int wv = ws[i];
        if (i < warp) wbase += wv;
        btot += wv;
    }
    if (tid == 0) {
        g_btotal[bid] = btot;
        __threadfence();
        ((volatile int*)g_sflag)[bid] = 1;
    }
    if (warp == 0) {
        int p = 0;
        for (int b = lane; b < bid; b += 32) {
            while (((volatile int*)g_sflag)[b] == 0) {}
            p += ((volatile int*)g_btotal)[b];
        }
#pragma unroll
        for (int off = 16; off > 0; off >>= 1)
            p += __shfl_xor_sync(0xffffffffu, p, off);
        if (lane == 0) s_prev = p;
    }
    __syncthreads();
    int offset = s_prev + wbase + (incl - tsum);
#pragma unroll
    for (int j = 0; j < 4; j++) {
        int idx = base + j;
        if (idx < N) {
            g_rowstart[idx] = offset;
            g_cursor[idx] = offset;
            float d = rsqrtf((float)(vals[j] + 1));
            g_dis[idx] = d;
            float4 gx;
            gx.x = x[idx * 3 + 0] * d;
            gx.y = x[idx * 3 + 1] * d;
            gx.z = x[idx * 3 + 2] * d;
            gx.w = d;
            g_gx[idx] = gx;
        }
        offset += vals[j];
    }
    if (bid == 0 && tid == 0) g_rowstart[N] = E;
}

__global__ void fill_kernel(const void* ei, int E) {
    int flag = detect64(ei);
    int e = blockIdx.x * blockDim.x + threadIdx.x;
    if (e >= E) return;
    int src = getIdx(ei, e, flag);
    int dst = getIdx(ei, (long long)E + e, flag);
    int pos = atomicAdd(&g_cursor[dst], 1);
    g_csrsrc[pos] = src;
}

// ======================= fused agg3 + pool + final ==========================
__device__ __forceinline__ void pool_flush(int cur, int sbase, int G, int lane,
                                           float4 a, float c,
                                           float* sacc, float* scnt) {
    if (cur < 0) return;
    int gl = cur - sbase;
    if (gl >= 0 && gl < GMAX) {
        atomicAdd(&sacc[gl * H + lane * 4 + 0], a.x);
        atomicAdd(&sacc[gl * H + lane * 4 + 1], a.y);
        atomicAdd(&sacc[gl * H + lane * 4 + 2], a.z);
        atomicAdd(&sacc[gl * H + lane * 4 + 3], a.w);
        if (lane == 0) atomicAdd(&scnt[gl], c);
    } else if (cur < G) {
        atomicAdd(&g_pool[cur * H + lane * 4 + 0], a.x);
        atomicAdd(&g_pool[cur * H + lane * 4 + 1], a.y);
        atomicAdd(&g_pool[cur * H + lane * 4 + 2], a.z);
        atomicAdd(&g_pool[cur * H + lane * 4 + 3], a.w);
        if (lane == 0) atomicAdd(&g_cnt[cur], c);
    }
}

__global__ void poolf_kernel(const float* __restrict__ g3,
                             const float* __restrict__ b3,
                             const void* batchp, const void* ei,
                             const float* __restrict__ Wl,
                             const float* __restrict__ bl,
                             float* __restrict__ out, int N, int G) {
    __shared__ float sacc[GMAX * H];
    __shared__ float scnt[GMAX];
    __shared__ int s_last;
    int tid = threadIdx.x, w = tid >> 5, lane = tid & 31;
    int flag = detect64(ei);   // batch shares dtype with edge_index
    int n0 = blockIdx.x * 128;

    for (int i = tid; i < GMAX * H; i += 256) sacc[i] = 0.f;
    if (tid < GMAX) scnt[tid] = 0.f;
    for (int i = tid; i < 128; i += 256) {
        int v = n0 + i;
        if (v < N) g_deg[v] = 0;
    }
    int sbase = getIdx(batchp, min(n0, N - 1), flag);
    __syncthreads();

    float4 racc = make_float4(0.f, 0.f, 0.f, 0.f);
    float rc = 0.f;
    int cur = -1;
    float4 bv = ((const float4*)b3)[lane];
    for (int t = 0; t < 16; t++) {
        int v = n0 + w * 16 + t;
        if (v >= N) break;
        int gI = getIdx(batchp, v, flag);
        if (gI != cur) {
            pool_flush(cur, sbase, G, lane, racc, rc, sacc, scnt);
            cur = gI;
            racc = make_float4(0.f, 0.f, 0.f, 0.f);
            rc = 0.f;
        }
        float4 a = make_float4(0.f, 0.f, 0.f, 0.f);
        int start = g_rowstart[v], end = g_rowstart[v + 1];
        for (int j0 = start; j0 < end; j0 += 32) {
            int nn = min(32, end - j0);
            int s = (j0 + lane < end) ? g_csrsrc[j0 + lane] : 0;
            for (int i = 0; i < nn; i++) {
                int si = __shfl_sync(0xffffffffu, s, i);
                float4 m = ((const float4*)(g3 + (size_t)si * H))[lane];
                a.x += m.x; a.y += m.y; a.z += m.z; a.w += m.w;
            }
        }
        float4 gv = ((const float4*)(g3 + (size_t)v * H))[lane];
        float dv = g_dis[v];
        racc.x += fmaxf(dv * (a.x + gv.x) + bv.x, 0.f);
        racc.y += fmaxf(dv * (a.y + gv.y) + bv.y, 0.f);
        racc.z += fmaxf(dv * (a.z + gv.z) + bv.z, 0.f);
        racc.w += fmaxf(dv * (a.w + gv.w) + bv.w, 0.f);
        rc += 1.f;
    }
    pool_flush(cur, sbase, G, lane, racc, rc, sacc, scnt);
    __syncthreads();

    for (int i = tid; i < GMAX * H; i += 256) {
        int gl = i >> 7;
        if (sbase + gl < G) {
            float val = sacc[i];
            if (val != 0.f) atomicAdd(&g_pool[(sbase + gl) * H + (i & 127)], val);
        }
    }
    if (tid < GMAX && sbase + tid < G && scnt[tid] != 0.f)
        atomicAdd(&g_cnt[sbase + tid], scnt[tid]);

    __threadfence();
    if (tid == 0) s_last = atomicAdd(&g_done, 1);
    __syncthreads();
    if (s_last == (int)gridDim.x - 1) {
        for (int idx = tid; idx < G * C; idx += 256) {
            int g = idx / C, c = idx % C;
            float cnt = __ldcg(&g_cnt[g]);
            float inv = 1.f / fmaxf(cnt, 1.f);
            float acc = 0.f;
#pragma unroll 8
            for (int k = 0; k < H; k++)
                acc += __ldcg(&g_pool[g * H + k]) * Wl[k * C + c];
            out[idx] = acc * inv + bl[c];
        }
        __syncthreads();
        for (int idx = tid; idx < G * H; idx += 256) g_pool[idx] = 0.f;
        if (tid < G) g_cnt[tid] = 0.f;
        if (tid == 0) g_done = 0;
    }
}

// ---------------------------------------------------------------------------
extern "C" void kernel_launch(void* const* d_in, const int* in_sizes, int n_in,
                              void* d_out, int out_size) {
    const float* x  = (const float*)d_in[0];
    const void*  ei = d_in[1];
    const void*  bt = d_in[2];
    const float* W1 = (const float*)d_in[3];
    const float* b1 = (const float*)d_in[4];
    const float* W2 = (const float*)d_in[5];
    const float* b2 = (const float*)d_in[6];
    const float* W3 = (const float*)d_in[7];
    const float* b3 = (const float*)d_in[8];
    const float* Wl = (const float*)d_in[9];
    const float* bl = (const float*)d_in[10];
    float* out = (float*)d_out;

    int N = in_sizes[0] / 3;
    int E = in_sizes[1] / 2;
    int G = out_size / C;
    if (N > MAXN) N = MAXN;
    if (E > MAXE) E = MAXE;

    cudaFuncSetAttribute(gemm2f_kernel,
                         cudaFuncAttributeMaxDynamicSharedMemorySize, S_TOTAL);
    cudaFuncSetAttribute(gemm3f_kernel,
                         cudaFuncAttributeMaxDynamicSharedMemorySize, S_TOTAL);

    float *bufA, *bufB;
    cudaGetSymbolAddress((void**)&bufA, g_bufA);
    cudaGetSymbolAddress((void**)&bufB, g_bufB);

    int nbE = (E + 255) / 256;
    int nbScan = (N + 1023) / 1024;     // <= 256, all co-resident
    int nbTile = (N + 63) / 64;
    int nbPool = (N + 127) / 128;

    hist_kernel<<<nbE, 256>>>(ei, E);
    scan_kernel<<<nbScan, 256>>>(x, N, E);
    wprep_kernel<<<64, 256>>>(W2, W3);
    fill_kernel<<<nbE, 256>>>(ei, E);
    gemm2f_kernel<<<nbTile, 256, S_TOTAL>>>(W1, b1, bufB, N);        // -> g2
    gemm3f_kernel<<<nbTile, 256, S_TOTAL>>>(b2, bufB, bufA, N);      // -> g3
    poolf_kernel<<<nbPool, 256>>>(bufA, b3, bt, ei, Wl, bl, out, N, G);
}